// round 11
// baseline (speedup 1.0000x reference)
#include <cuda_runtime.h>
#include <cuda_bf16.h>
#include <math.h>
#include <stdint.h>

#define BB 64
#define TT 128
#define IDIM 4096
#define HH 1024
#define FOURH 4096
#define K0 2048
#define K1 3072
#define KSPLIT 4
#define GRID_N 128

// ---- scratch: chunk-tiled, swizzle pre-baked (16B group g of row r at g^(r&7)) ----
__device__ __align__(128) float g_XZ0[(size_t)TT * BB * FOURH];
__device__ __align__(128) __nv_bfloat16 g_Axh[(size_t)BB * TT * IDIM];
__device__ __align__(128) __nv_bfloat16 g_Axl[(size_t)BB * TT * IDIM];
__device__ __align__(128) __nv_bfloat16 g_Bwh[(size_t)FOURH * IDIM];
__device__ __align__(128) __nv_bfloat16 g_Bwl[(size_t)FOURH * IDIM];
__device__ __align__(128) __nv_bfloat16 g_W0h[(size_t)FOURH * K0];
__device__ __align__(128) __nv_bfloat16 g_W0l[(size_t)FOURH * K0];
__device__ __align__(128) __nv_bfloat16 g_W1h[(size_t)FOURH * K1];
__device__ __align__(128) __nv_bfloat16 g_W1l[(size_t)FOURH * K1];
__device__ float g_b0r[FOURH];
__device__ float g_b1r[FOURH];
__device__ __align__(128) __nv_bfloat16 g_S0h[BB * K0];
__device__ __align__(128) __nv_bfloat16 g_S0l[BB * K0];
__device__ __align__(128) __nv_bfloat16 g_S1h[BB * K1];
__device__ __align__(128) __nv_bfloat16 g_S1l[BB * K1];
__device__ float g_C0[BB * HH];
__device__ float g_C1[BB * HH];
__device__ float g_P0[KSPLIT][BB * FOURH];   // gemm0 partials (epi0 reads)
__device__ float g_P1[KSPLIT][BB * FOURH];   // gemm1 partials (epi1 reads)
__device__ unsigned int g_arr[GRID_N];       // flag-tree barrier: arrivals
__device__ unsigned int g_rel;               // flag-tree barrier: release

#define AX_OFF(r,k) ( (((size_t)(((r)>>7)*64+((k)>>6)))<<14) + (size_t)(((r)&127)<<7) + (size_t)(((((k)&63)*2)^(((r)&7)<<4))) )
#define BW_OFF(n,k) ( (((size_t)(((n)>>7)*64+((k)>>6)))<<14) + (size_t)(((n)&127)<<7) + (size_t)(((((k)&63)*2)^(((n)&7)<<4))) )
#define W0_OFF(n,k) ( (((size_t)(((n)>>7)*32+((k)>>6)))<<14) + (size_t)(((n)&127)<<7) + (size_t)(((((k)&63)*2)^(((n)&7)<<4))) )
#define W1_OFF(n,k) ( (((size_t)(((n)>>7)*48+((k)>>6)))<<14) + (size_t)(((n)&127)<<7) + (size_t)(((((k)&63)*2)^(((n)&7)<<4))) )
#define ST_OFF(k,b) ( (((size_t)((k)>>6))<<13) + (size_t)((b)<<7) + (size_t)(((((k)&63)*2)^(((b)&7)<<4))) )

// ---- PTX helpers ----
__device__ __forceinline__ uint32_t smem_u32(const void* p) {
    uint32_t a;
    asm("{ .reg .u64 t; cvta.to.shared.u64 t, %1; cvt.u32.u64 %0, t; }" : "=r"(a) : "l"(p));
    return a;
}
__device__ __forceinline__ void mbar_init(uint32_t m, uint32_t c) {
    asm volatile("mbarrier.init.shared.b64 [%0], %1;" :: "r"(m), "r"(c) : "memory");
}
__device__ __forceinline__ void mbar_expect(uint32_t m, uint32_t b) {
    asm volatile("mbarrier.arrive.expect_tx.shared.b64 _, [%0], %1;" :: "r"(m), "r"(b) : "memory");
}
__device__ __forceinline__ void mbar_wait(uint32_t m, uint32_t par) {
    asm volatile(
        "{\n\t.reg .pred P;\nWL%=:\n\t"
        "mbarrier.try_wait.parity.shared.b64 P, [%0], %1;\n\t"
        "@P bra.uni WD%=;\n\tbra.uni WL%=;\nWD%=:\n\t}"
        :: "r"(m), "r"(par) : "memory");
}
__device__ __forceinline__ void bulk_cp(uint32_t d, const void* s, uint32_t b, uint32_t m) {
    asm volatile("cp.async.bulk.shared::cta.global.mbarrier::complete_tx::bytes [%0], [%1], %2, [%3];"
                 :: "r"(d), "l"(s), "r"(b), "r"(m) : "memory");
}
__device__ __forceinline__ void ldsm_x4(uint32_t* r, uint32_t a) {
    asm volatile("ldmatrix.sync.aligned.m8n8.x4.shared.b16 {%0,%1,%2,%3}, [%4];"
                 : "=r"(r[0]), "=r"(r[1]), "=r"(r[2]), "=r"(r[3]) : "r"(a));
}
__device__ __forceinline__ void ldsm_x2(uint32_t* r, uint32_t a) {
    asm volatile("ldmatrix.sync.aligned.m8n8.x2.shared.b16 {%0,%1}, [%2];"
                 : "=r"(r[0]), "=r"(r[1]) : "r"(a));
}
__device__ __forceinline__ void mma_bf16(float* d, const uint32_t* a, const uint32_t* b) {
    asm volatile("mma.sync.aligned.m16n8k16.row.col.f32.bf16.bf16.f32 "
        "{%0,%1,%2,%3}, {%4,%5,%6,%7}, {%8,%9}, {%0,%1,%2,%3};"
        : "+f"(d[0]), "+f"(d[1]), "+f"(d[2]), "+f"(d[3])
        : "r"(a[0]), "r"(a[1]), "r"(a[2]), "r"(a[3]), "r"(b[0]), "r"(b[1]));
}
__device__ __forceinline__ void split_bf(float v, __nv_bfloat16& h, __nv_bfloat16& l) {
    h = __float2bfloat16_rn(v);
    l = __float2bfloat16_rn(v - __bfloat162float(h));
}
__device__ __forceinline__ uint32_t pack_bf2(__nv_bfloat16 a, __nv_bfloat16 b) {
    union { __nv_bfloat16 h[2]; uint32_t u; } t; t.h[0] = a; t.h[1] = b; return t.u;
}
__device__ __forceinline__ float sig_(float z) { return 1.0f / (1.0f + expf(-z)); }

// flag-tree grid barrier: per-CTA arrival flags, CTA0 gathers, single release word
__device__ __forceinline__ void grid_sync(int cta, int tid, unsigned int seq) {
    asm volatile("fence.proxy.async;" ::: "memory");
    __syncthreads();
    if (tid == 0) {
        __threadfence();
        __stcg(&g_arr[cta], seq);
    }
    if (cta == 0) {
        if (tid < GRID_N) {
            while (__ldcg(&g_arr[tid]) < seq) __nanosleep(20);
        }
        __syncthreads();
        if (tid == 0) { __threadfence(); __stcg(&g_rel, seq); }
    }
    if (tid == 0) {
        while (__ldcg(&g_rel) < seq) __nanosleep(20);
        __threadfence();
    }
    __syncthreads();
}

// ---- prep kernels (identical numerics) ----
__global__ void conv_x(const float* __restrict__ x) {
    size_t i0 = ((size_t)blockIdx.x * 256 + threadIdx.x) * 4;
    float4 v = *(const float4*)(x + i0);
    union { __nv_bfloat16 b[4]; uint2 u; } ph, pl;
    split_bf(v.x, ph.b[0], pl.b[0]); split_bf(v.y, ph.b[1], pl.b[1]);
    split_bf(v.z, ph.b[2], pl.b[2]); split_bf(v.w, ph.b[3], pl.b[3]);
    size_t off = AX_OFF((int)(i0 >> 12), (int)(i0 & 4095));
    *(uint2*)((char*)g_Axh + off) = ph.u;
    *(uint2*)((char*)g_Axl + off) = pl.u;
}

__global__ void repack_wx0b(const float* __restrict__ Wx0, const float* __restrict__ b0) {
    int n = blockIdx.x, g = n & 3, h = n >> 2;
    const float* src = Wx0 + (size_t)(g * HH + h) * IDIM;
    for (int i = threadIdx.x; i < IDIM; i += blockDim.x) {
        __nv_bfloat16 hh, ll; split_bf(src[i], hh, ll);
        size_t off = BW_OFF(n, i);
        *(__nv_bfloat16*)((char*)g_Bwh + off) = hh;
        *(__nv_bfloat16*)((char*)g_Bwl + off) = ll;
    }
    if (threadIdx.x == 0) g_b0r[n] = b0[g * HH + h];
}

__global__ void repack_w0(const float* __restrict__ Uh0, const float* __restrict__ Vc0) {
    int n = blockIdx.x, g = n & 3, h = n >> 2;
    const float* u = Uh0 + (size_t)(g * HH + h) * HH;
    for (int k = threadIdx.x; k < HH; k += blockDim.x) {
        __nv_bfloat16 hh, ll; split_bf(u[k], hh, ll);
        size_t off = W0_OFF(n, k);
        *(__nv_bfloat16*)((char*)g_W0h + off) = hh;
        *(__nv_bfloat16*)((char*)g_W0l + off) = ll;
    }
    int vg = (g == 0) ? 0 : (g == 1) ? 1 : (g == 3) ? 2 : -1;
    const float* v = (vg >= 0) ? (Vc0 + (size_t)(vg * HH + h) * HH) : 0;
    for (int k = threadIdx.x; k < HH; k += blockDim.x) {
        float val = (vg >= 0) ? v[k] : 0.0f;
        __nv_bfloat16 hh, ll; split_bf(val, hh, ll);
        size_t off = W0_OFF(n, HH + k);
        *(__nv_bfloat16*)((char*)g_W0h + off) = hh;
        *(__nv_bfloat16*)((char*)g_W0l + off) = ll;
    }
}

__global__ void repack_w1(const float* __restrict__ Wx1, const float* __restrict__ Uh1,
                          const float* __restrict__ Vc1, const float* __restrict__ b1) {
    int n = blockIdx.x, g = n & 3, h = n >> 2;
    const float* wx = Wx1 + (size_t)(g * HH + h) * HH;
    const float* uh = Uh1 + (size_t)(g * HH + h) * HH;
    for (int k = threadIdx.x; k < HH; k += blockDim.x) {
        __nv_bfloat16 hh, ll;
        split_bf(wx[k], hh, ll);
        size_t off = W1_OFF(n, k);
        *(__nv_bfloat16*)((char*)g_W1h + off) = hh;
        *(__nv_bfloat16*)((char*)g_W1l + off) = ll;
        split_bf(uh[k], hh, ll);
        off = W1_OFF(n, HH + k);
        *(__nv_bfloat16*)((char*)g_W1h + off) = hh;
        *(__nv_bfloat16*)((char*)g_W1l + off) = ll;
    }
    int vg = (g == 0) ? 0 : (g == 1) ? 1 : (g == 3) ? 2 : -1;
    const float* v = (vg >= 0) ? (Vc1 + (size_t)(vg * HH + h) * HH) : 0;
    for (int k = threadIdx.x; k < HH; k += blockDim.x) {
        float val = (vg >= 0) ? v[k] : 0.0f;
        __nv_bfloat16 hh, ll; split_bf(val, hh, ll);
        size_t off = W1_OFF(n, 2 * HH + k);
        *(__nv_bfloat16*)((char*)g_W1h + off) = hh;
        *(__nv_bfloat16*)((char*)g_W1l + off) = ll;
    }
    if (threadIdx.x == 0) g_b1r[n] = b1[g * HH + h];
}

__global__ void init_state(const float* __restrict__ h0, const float* __restrict__ c0) {
    int idx = blockIdx.x * blockDim.x + threadIdx.x;
    if (idx < GRID_N) g_arr[idx] = 0u;
    if (idx == 0) g_rel = 0u;
    int b = idx >> 10, h = idx & 1023;
    __nv_bfloat16 hh, ll; float v; size_t off;
    v = h0[b * HH + h]; split_bf(v, hh, ll);
    off = ST_OFF(h, b);
    *(__nv_bfloat16*)((char*)g_S0h + off) = hh; *(__nv_bfloat16*)((char*)g_S0l + off) = ll;
    v = c0[b * HH + h]; g_C0[idx] = v; split_bf(v, hh, ll);
    off = ST_OFF(HH + h, b);
    *(__nv_bfloat16*)((char*)g_S0h + off) = hh; *(__nv_bfloat16*)((char*)g_S0l + off) = ll;
    v = h0[BB * HH + b * HH + h]; split_bf(v, hh, ll);
    off = ST_OFF(HH + h, b);
    *(__nv_bfloat16*)((char*)g_S1h + off) = hh; *(__nv_bfloat16*)((char*)g_S1l + off) = ll;
    v = c0[BB * HH + b * HH + h]; g_C1[idx] = v; split_bf(v, hh, ll);
    off = ST_OFF(2 * HH + h, b);
    *(__nv_bfloat16*)((char*)g_S1h + off) = hh; *(__nv_bfloat16*)((char*)g_S1l + off) = ll;
    off = ST_OFF(h, b);
    *(__nv_bfloat16*)((char*)g_S1h + off) = __float2bfloat16(0.0f);
    *(__nv_bfloat16*)((char*)g_S1l + off) = __float2bfloat16(0.0f);
}

// ---- phase A: bf16 3-term, CTA 128x128, 64 chunks of k64; 3 stages ----
#define XZ_STAGE 65536u
__global__ __launch_bounds__(256) void gemm_xz_mma() {
    extern __shared__ __align__(128) char dsm[];
    __shared__ __align__(8) unsigned long long mbars[3];
    const int tid = threadIdx.x, w = tid >> 5, l = tid & 31;
    const int wm = w & 3, wn = w >> 2;
    const int m0 = blockIdx.y * 128, n0 = blockIdx.x * 128;
    const uint32_t sb = smem_u32(dsm), mb0 = smem_u32(mbars);
    if (tid == 0) { mbar_init(mb0, 1); mbar_init(mb0 + 8, 1); mbar_init(mb0 + 16, 1); }
    __syncthreads();
    const char* Ah = (const char*)g_Axh + ((size_t)blockIdx.y * 64) * 16384;
    const char* Al = (const char*)g_Axl + ((size_t)blockIdx.y * 64) * 16384;
    const char* Bh = (const char*)g_Bwh + ((size_t)blockIdx.x * 64) * 16384;
    const char* Bl = (const char*)g_Bwl + ((size_t)blockIdx.x * 64) * 16384;
    auto issue = [&](int kc) {
        int st = kc % 3;
        uint32_t d = sb + st * XZ_STAGE, mb = mb0 + st * 8;
        mbar_expect(mb, XZ_STAGE);
        bulk_cp(d,         Ah + (size_t)kc * 16384, 16384, mb);
        bulk_cp(d + 16384, Al + (size_t)kc * 16384, 16384, mb);
        bulk_cp(d + 32768, Bh + (size_t)kc * 16384, 16384, mb);
        bulk_cp(d + 49152, Bl + (size_t)kc * 16384, 16384, mb);
    };
    if (tid == 0) { issue(0); issue(1); }

    float acc[2][8][4];
#pragma unroll
    for (int a = 0; a < 2; a++)
#pragma unroll
        for (int b = 0; b < 8; b++)
#pragma unroll
            for (int c = 0; c < 4; c++) acc[a][b][c] = 0.0f;

    int uses[3] = {0, 0, 0};
    for (int kc = 0; kc < 64; kc++) {
        const int st = kc % 3;
        const uint32_t stb = sb + st * XZ_STAGE;
        mbar_wait(mb0 + st * 8, uses[st] & 1); uses[st]++;
        if (tid == 0 && kc + 2 < 64) issue(kc + 2);
#pragma unroll
        for (int ks = 0; ks < 4; ks++) {
            const int kb = ks * 32;
            uint32_t ah[2][4], al[2][4];
#pragma unroll
            for (int mt = 0; mt < 2; mt++) {
                int row = wm * 32 + mt * 16 + (l & 15);
                uint32_t ra = stb + (uint32_t)(row * 128 + ((kb + ((l >> 4) << 4)) ^ ((row & 7) << 4)));
                ldsm_x4(ah[mt], ra);
                ldsm_x4(al[mt], ra + 16384);
            }
#pragma unroll
            for (int nt = 0; nt < 8; nt++) {
                int row = wn * 64 + nt * 8 + (l & 7);
                uint32_t rb = stb + 32768 +
                    (uint32_t)(row * 128 + ((kb + (((l >> 3) & 1) << 4)) ^ ((row & 7) << 4)));
                uint32_t bh[2], bl[2];
                ldsm_x2(bh, rb);
                ldsm_x2(bl, rb + 16384);
#pragma unroll
                for (int mt = 0; mt < 2; mt++) {
                    mma_bf16(acc[mt][nt], ah[mt], bh);
                    mma_bf16(acc[mt][nt], ah[mt], bl);
                    mma_bf16(acc[mt][nt], al[mt], bh);
                }
            }
        }
        __syncthreads();
    }

    const int r0 = l >> 2, cp2 = (l & 3) * 2;
#pragma unroll
    for (int mt = 0; mt < 2; mt++)
#pragma unroll
        for (int half = 0; half < 2; half++) {
            int gm = m0 + wm * 32 + mt * 16 + r0 + half * 8;
            int t = gm & (TT - 1), b = gm >> 7;
            float* dst = g_XZ0 + ((size_t)(t * BB + b) << 12);
#pragma unroll
            for (int nt = 0; nt < 8; nt++) {
                int gc = n0 + wn * 64 + nt * 8 + cp2;
                float2 v;
                v.x = acc[mt][nt][half * 2 + 0] + g_b0r[gc];
                v.y = acc[mt][nt][half * 2 + 1] + g_b0r[gc + 1];
                *(float2*)(dst + gc) = v;
            }
        }
}

// ---- persistent loop: staging + GEMM (3 stages of 48KB) ----
#define LP_STAGE 49152u
#define LOOP_SMEM (3u * LP_STAGE)
template <int WHICH>
__device__ __forceinline__ void issueLP(int cta, int kc, uint32_t sb, uint32_t mb0) {
    constexpr int NKC = (WHICH ? K1 : K0) / 64;
    constexpr int NC  = NKC / KSPLIT;
    const char* Sh = (const char*)(WHICH ? g_S1h : g_S0h);
    const char* Sl = (const char*)(WHICH ? g_S1l : g_S0l);
    const char* Wh = (const char*)(WHICH ? g_W1h : g_W0h);
    const char* Wl = (const char*)(WHICH ? g_W1l : g_W0l);
    const int nblk = cta & 31, kseg = cta >> 5;
    const int kcA = kseg * NC + kc;
    int st = kc % 3;
    uint32_t d = sb + st * LP_STAGE, mb = mb0 + st * 8;
    mbar_expect(mb, LP_STAGE);
    bulk_cp(d,         Sh + (size_t)kcA * 8192, 8192, mb);
    bulk_cp(d + 8192,  Sl + (size_t)kcA * 8192, 8192, mb);
    bulk_cp(d + 16384, Wh + ((size_t)nblk * NKC + kcA) * 16384, 16384, mb);
    bulk_cp(d + 32768, Wl + ((size_t)nblk * NKC + kcA) * 16384, 16384, mb);
}

template <int WHICH>
__device__ __forceinline__ void gemm_phase(int cta, int tid, uint32_t sb, uint32_t mb0, int* uses) {
    constexpr int NC = ((WHICH ? K1 : K0) / 64) / KSPLIT;   // 8 or 12
    const int w = tid >> 5, l = tid & 31;
    const int wm = w & 3, wn = w >> 2;
    const int nblk = cta & 31, kseg = cta >> 5;

    float acc[8][4];
#pragma unroll
    for (int b = 0; b < 8; b++)
#pragma unroll
        for (int c = 0; c < 4; c++) acc[b][c] = 0.0f;

    for (int kc = 0; kc < NC; kc++) {
        const int st = kc % 3;
        const uint32_t stb = sb + st * LP_STAGE;
        mbar_wait(mb0 + st * 8, uses[st] & 1); uses[st]++;
        if (tid == 0 && kc + 2 < NC) issueLP<WHICH>(cta, kc + 2, sb, mb0);
#pragma unroll
        for (int ks = 0; ks < 4; ks++) {
            const int kb = ks * 32;
            uint32_t ah[4], al[4];
            int arow = wm * 16 + (l & 15);
            uint32_t ra = stb + (uint32_t)(arow * 128 + ((kb + ((l >> 4) << 4)) ^ ((arow & 7) << 4)));
            ldsm_x4(ah, ra);
            ldsm_x4(al, ra + 8192);
#pragma unroll
            for (int nt = 0; nt < 8; nt++) {
                int brow = wn * 64 + nt * 8 + (l & 7);
                uint32_t rb = stb + 16384 +
                    (uint32_t)(brow * 128 + ((kb + (((l >> 3) & 1) << 4)) ^ ((brow & 7) << 4)));
                uint32_t bh[2], bl[2];
                ldsm_x2(bh, rb);
                ldsm_x2(bl, rb + 16384);
                mma_bf16(acc[nt], ah, bh);
                mma_bf16(acc[nt], ah, bl);
                mma_bf16(acc[nt], al, bh);
            }
        }
        __syncthreads();
    }

    float* dst = (WHICH ? g_P1 : g_P0)[kseg];
    const int r0 = l >> 2, cp2 = (l & 3) * 2;
#pragma unroll
    for (int half = 0; half < 2; half++) {
        int b = wm * 16 + r0 + half * 8;
#pragma unroll
        for (int nt = 0; nt < 8; nt++) {
            int gc = nblk * 128 + wn * 64 + nt * 8 + cp2;
            *(float2*)(dst + ((size_t)b << 12) + gc) =
                make_float2(acc[nt][half * 2 + 0], acc[nt][half * 2 + 1]);
        }
    }
}

// epi1 for step t: reads g_P1, updates cB, writes S1 h/c (+ output row)
__device__ __forceinline__ void do_epi1(int t, int b, int h0i, float* cB,
                                        float* out, float* hn_base, float* cn_base) {
    float hn[2], cn[2];
#pragma unroll
    for (int j = 0; j < 2; j++) {
        int h = h0i + j, nb = h << 2;
        float4 z = *(const float4*)&g_b1r[nb];
#pragma unroll
        for (int ks = 0; ks < KSPLIT; ks++) {
            float4 pp = __ldcg((const float4*)&g_P1[ks][((size_t)b << 12) + nb]);
            z.x += pp.x; z.y += pp.y; z.z += pp.z; z.w += pp.w;
        }
        float ig = sig_(z.x), fg = sig_(z.y), gg = tanhf(z.z), og = sig_(z.w);
        cn[j] = fg * cB[j] + ig * gg;
        hn[j] = og * tanhf(cn[j]);
        cB[j] = cn[j];
    }
    __nv_bfloat16 a0, a1, b0, b1, c0h, c0l, c1h, c1l;
    split_bf(hn[0], a0, a1); split_bf(hn[1], b0, b1);
    split_bf(cn[0], c0h, c0l); split_bf(cn[1], c1h, c1l);
    size_t off = ST_OFF(HH + h0i, b);
    *(uint32_t*)((char*)g_S1h + off) = pack_bf2(a0, b0);
    *(uint32_t*)((char*)g_S1l + off) = pack_bf2(a1, b1);
    off = ST_OFF(2 * HH + h0i, b);
    *(uint32_t*)((char*)g_S1h + off) = pack_bf2(c0h, c1h);
    *(uint32_t*)((char*)g_S1l + off) = pack_bf2(c0l, c1l);
    float* op = out + ((size_t)b * TT + t) * HH + h0i;
    op[0] = hn[0]; op[1] = hn[1];
    if (t == TT - 1) {
        hn_base[BB * HH + b * HH + h0i] = hn[0]; hn_base[BB * HH + b * HH + h0i + 1] = hn[1];
        cn_base[BB * HH + b * HH + h0i] = cn[0]; cn_base[BB * HH + b * HH + h0i + 1] = cn[1];
    }
}

__global__ __launch_bounds__(256) void rnn_loop(float* __restrict__ out) {
    extern __shared__ __align__(128) char dsm[];
    __shared__ __align__(8) unsigned long long mbars[3];
    const int cta = blockIdx.x, tid = threadIdx.x;
    const uint32_t sb = smem_u32(dsm);
    const uint32_t mb0 = smem_u32(mbars);
    if (tid == 0) { mbar_init(mb0, 1); mbar_init(mb0 + 8, 1); mbar_init(mb0 + 16, 1); }
    __syncthreads();

    const int idx0 = (cta * 256 + tid) * 2;
    const int b = idx0 >> 10, h0i = idx0 & 1023;
    float cA[2] = { g_C0[idx0], g_C0[idx0 + 1] };
    float cB[2] = { g_C1[idx0], g_C1[idx0 + 1] };
    float* hn_base = out + (size_t)BB * TT * HH;
    float* cn_base = hn_base + 2 * BB * HH;
    unsigned int seq = 0;
    int uses[3] = {0, 0, 0};

    for (int t = 0; t < TT; t++) {
        // merged phase: stage gemm0 (S0 ready 2 syncs ago), overlap with epi1(t-1)
        if (tid == 0) { issueLP<0>(cta, 0, sb, mb0); issueLP<0>(cta, 1, sb, mb0); }
        if (t > 0) do_epi1(t - 1, b, h0i, cB, out, hn_base, cn_base);
        gemm_phase<0>(cta, tid, sb, mb0, uses);          // writes P0
        grid_sync(cta, tid, ++seq);

        { // epi0: reads P0, writes S0(t+1) h/c + S1 ha + C0
            float hn[2], cn[2];
#pragma unroll
            for (int j = 0; j < 2; j++) {
                int h = h0i + j, nb = h << 2;
                float4 z = *(const float4*)&g_XZ0[((size_t)(t * BB + b) << 12) + nb];
#pragma unroll
                for (int ks = 0; ks < KSPLIT; ks++) {
                    float4 pp = __ldcg((const float4*)&g_P0[ks][((size_t)b << 12) + nb]);
                    z.x += pp.x; z.y += pp.y; z.z += pp.z; z.w += pp.w;
                }
                float ig = sig_(z.x), fg = sig_(z.y), gg = tanhf(z.z), og = sig_(z.w);
                cn[j] = fg * cA[j] + ig * gg;
                hn[j] = og * tanhf(cn[j]);
                cA[j] = cn[j];
            }
            __nv_bfloat16 a0, a1, b0_, b1_, c0h, c0l, c1h, c1l;
            split_bf(hn[0], a0, a1); split_bf(hn[1], b0_, b1_);
            split_bf(cn[0], c0h, c0l); split_bf(cn[1], c1h, c1l);
            uint32_t hp = pack_bf2(a0, b0_), lp = pack_bf2(a1, b1_);
            size_t off = ST_OFF(h0i, b);
            *(uint32_t*)((char*)g_S0h + off) = hp; *(uint32_t*)((char*)g_S0l + off) = lp;
            *(uint32_t*)((char*)g_S1h + off) = hp; *(uint32_t*)((char*)g_S1l + off) = lp;
            off = ST_OFF(HH + h0i, b);
            *(uint32_t*)((char*)g_S0h + off) = pack_bf2(c0h, c1h);
            *(uint32_t*)((char*)g_S0l + off) = pack_bf2(c0l, c1l);
            if (t == TT - 1) {
                hn_base[b * HH + h0i] = hn[0]; hn_base[b * HH + h0i + 1] = hn[1];
                cn_base[b * HH + h0i] = cn[0]; cn_base[b * HH + h0i + 1] = cn[1];
            }
        }
        grid_sync(cta, tid, ++seq);

        if (tid == 0) { issueLP<1>(cta, 0, sb, mb0); issueLP<1>(cta, 1, sb, mb0); }
        gemm_phase<1>(cta, tid, sb, mb0, uses);          // writes P1
        grid_sync(cta, tid, ++seq);
    }
    do_epi1(TT - 1, b, h0i, cB, out, hn_base, cn_base);
}

extern "C" void kernel_launch(void* const* d_in, const int* in_sizes, int n_in,
                              void* d_out, int out_size) {
    (void)in_sizes; (void)n_in; (void)out_size;
    const float* x   = (const float*)d_in[0];
    const float* h0  = (const float*)d_in[1];
    const float* c0  = (const float*)d_in[2];
    const float* Wx0 = (const float*)d_in[3];
    const float* Uh0 = (const float*)d_in[4];
    const float* Vc0 = (const float*)d_in[5];
    const float* b0  = (const float*)d_in[6];
    const float* Wx1 = (const float*)d_in[7];
    const float* Uh1 = (const float*)d_in[8];
    const float* Vc1 = (const float*)d_in[9];
    const float* b1  = (const float*)d_in[10];
    float* out = (float*)d_out;

    cudaFuncSetAttribute(gemm_xz_mma, cudaFuncAttributeMaxDynamicSharedMemorySize, 3 * XZ_STAGE);
    cudaFuncSetAttribute(rnn_loop,    cudaFuncAttributeMaxDynamicSharedMemorySize, LOOP_SMEM);

    conv_x     <<<(BB * TT * IDIM) / (4 * 256), 256>>>(x);
    repack_wx0b<<<FOURH, 256>>>(Wx0, b0);
    repack_w0  <<<FOURH, 256>>>(Uh0, Vc0);
    repack_w1  <<<FOURH, 256>>>(Wx1, Uh1, Vc1, b1);
    init_state <<<(BB * HH) / 256, 256>>>(h0, c0);

    gemm_xz_mma<<<dim3(FOURH / 128, (BB * TT) / 128), 256, 3 * XZ_STAGE>>>();

    rnn_loop<<<GRID_N, 256, LOOP_SMEM>>>(out);
}

// round 12
// speedup vs baseline: 1.0158x; 1.0158x over previous
#include <cuda_runtime.h>
#include <cuda_bf16.h>
#include <math.h>
#include <stdint.h>

#define BB 64
#define TT 128
#define IDIM 4096
#define HH 1024
#define FOURH 4096
#define K0 2048
#define K1 3072
#define KSPLIT 4
#define GRID_N 128

// ---- scratch: chunk-tiled, swizzle pre-baked (16B group g of row r at g^(r&7)) ----
__device__ __align__(128) float g_XZ0[(size_t)TT * BB * FOURH];
__device__ __align__(128) __nv_bfloat16 g_Axh[(size_t)BB * TT * IDIM];
__device__ __align__(128) __nv_bfloat16 g_Axl[(size_t)BB * TT * IDIM];
__device__ __align__(128) __nv_bfloat16 g_Bwh[(size_t)FOURH * IDIM];
__device__ __align__(128) __nv_bfloat16 g_Bwl[(size_t)FOURH * IDIM];
__device__ __align__(128) __nv_bfloat16 g_W0h[(size_t)FOURH * K0];
__device__ __align__(128) __nv_bfloat16 g_W0l[(size_t)FOURH * K0];
__device__ __align__(128) __nv_bfloat16 g_W1h[(size_t)FOURH * K1];
__device__ __align__(128) __nv_bfloat16 g_W1l[(size_t)FOURH * K1];
__device__ float g_b0r[FOURH];
__device__ float g_b1r[FOURH];
__device__ __align__(128) __nv_bfloat16 g_S0h[BB * K0];
__device__ __align__(128) __nv_bfloat16 g_S0l[BB * K0];
__device__ __align__(128) __nv_bfloat16 g_S1h[BB * K1];
__device__ __align__(128) __nv_bfloat16 g_S1l[BB * K1];
__device__ float g_C0[BB * HH];
__device__ float g_C1[BB * HH];
__device__ float g_P[KSPLIT][BB * FOURH];
__device__ unsigned int g_bar;

#define AX_OFF(r,k) ( (((size_t)(((r)>>7)*64+((k)>>6)))<<14) + (size_t)(((r)&127)<<7) + (size_t)(((((k)&63)*2)^(((r)&7)<<4))) )
#define BW_OFF(n,k) ( (((size_t)(((n)>>7)*64+((k)>>6)))<<14) + (size_t)(((n)&127)<<7) + (size_t)(((((k)&63)*2)^(((n)&7)<<4))) )
#define W0_OFF(n,k) ( (((size_t)(((n)>>7)*32+((k)>>6)))<<14) + (size_t)(((n)&127)<<7) + (size_t)(((((k)&63)*2)^(((n)&7)<<4))) )
#define W1_OFF(n,k) ( (((size_t)(((n)>>7)*48+((k)>>6)))<<14) + (size_t)(((n)&127)<<7) + (size_t)(((((k)&63)*2)^(((n)&7)<<4))) )
#define ST_OFF(k,b) ( (((size_t)((k)>>6))<<13) + (size_t)((b)<<7) + (size_t)(((((k)&63)*2)^(((b)&7)<<4))) )

// ---- PTX helpers ----
__device__ __forceinline__ uint32_t smem_u32(const void* p) {
    uint32_t a;
    asm("{ .reg .u64 t; cvta.to.shared.u64 t, %1; cvt.u32.u64 %0, t; }" : "=r"(a) : "l"(p));
    return a;
}
__device__ __forceinline__ void mbar_init(uint32_t m, uint32_t c) {
    asm volatile("mbarrier.init.shared.b64 [%0], %1;" :: "r"(m), "r"(c) : "memory");
}
__device__ __forceinline__ void mbar_expect(uint32_t m, uint32_t b) {
    asm volatile("mbarrier.arrive.expect_tx.shared.b64 _, [%0], %1;" :: "r"(m), "r"(b) : "memory");
}
__device__ __forceinline__ void mbar_wait(uint32_t m, uint32_t par) {
    asm volatile(
        "{\n\t.reg .pred P;\nWL%=:\n\t"
        "mbarrier.try_wait.parity.shared.b64 P, [%0], %1;\n\t"
        "@P bra.uni WD%=;\n\tbra.uni WL%=;\nWD%=:\n\t}"
        :: "r"(m), "r"(par) : "memory");
}
__device__ __forceinline__ void bulk_cp(uint32_t d, const void* s, uint32_t b, uint32_t m) {
    asm volatile("cp.async.bulk.shared::cta.global.mbarrier::complete_tx::bytes [%0], [%1], %2, [%3];"
                 :: "r"(d), "l"(s), "r"(b), "r"(m) : "memory");
}
__device__ __forceinline__ void ldsm_x4(uint32_t* r, uint32_t a) {
    asm volatile("ldmatrix.sync.aligned.m8n8.x4.shared.b16 {%0,%1,%2,%3}, [%4];"
                 : "=r"(r[0]), "=r"(r[1]), "=r"(r[2]), "=r"(r[3]) : "r"(a));
}
__device__ __forceinline__ void ldsm_x2(uint32_t* r, uint32_t a) {
    asm volatile("ldmatrix.sync.aligned.m8n8.x2.shared.b16 {%0,%1}, [%2];"
                 : "=r"(r[0]), "=r"(r[1]) : "r"(a));
}
__device__ __forceinline__ void mma_bf16(float* d, const uint32_t* a, const uint32_t* b) {
    asm volatile("mma.sync.aligned.m16n8k16.row.col.f32.bf16.bf16.f32 "
        "{%0,%1,%2,%3}, {%4,%5,%6,%7}, {%8,%9}, {%0,%1,%2,%3};"
        : "+f"(d[0]), "+f"(d[1]), "+f"(d[2]), "+f"(d[3])
        : "r"(a[0]), "r"(a[1]), "r"(a[2]), "r"(a[3]), "r"(b[0]), "r"(b[1]));
}
__device__ __forceinline__ void split_bf(float v, __nv_bfloat16& h, __nv_bfloat16& l) {
    h = __float2bfloat16_rn(v);
    l = __float2bfloat16_rn(v - __bfloat162float(h));
}
__device__ __forceinline__ float sig_(float z) { return 1.0f / (1.0f + expf(-z)); }

__device__ __forceinline__ void grid_sync(unsigned int target) {
    asm volatile("fence.proxy.async;" ::: "memory");
    __syncthreads();
    if (threadIdx.x == 0) {
        __threadfence();
        atomicAdd(&g_bar, 1u);
        while (__ldcg(&g_bar) < target) __nanosleep(32);
        __threadfence();
    }
    __syncthreads();
}

// ---- prep kernels (identical numerics to R7) ----
__global__ void conv_x(const float* __restrict__ x) {
    size_t i0 = ((size_t)blockIdx.x * 256 + threadIdx.x) * 4;
    float4 v = *(const float4*)(x + i0);
    union { __nv_bfloat16 b[4]; uint2 u; } ph, pl;
    split_bf(v.x, ph.b[0], pl.b[0]); split_bf(v.y, ph.b[1], pl.b[1]);
    split_bf(v.z, ph.b[2], pl.b[2]); split_bf(v.w, ph.b[3], pl.b[3]);
    size_t off = AX_OFF((int)(i0 >> 12), (int)(i0 & 4095));
    *(uint2*)((char*)g_Axh + off) = ph.u;
    *(uint2*)((char*)g_Axl + off) = pl.u;
}

__global__ void repack_wx0b(const float* __restrict__ Wx0, const float* __restrict__ b0) {
    int n = blockIdx.x, g = n & 3, h = n >> 2;
    const float* src = Wx0 + (size_t)(g * HH + h) * IDIM;
    for (int i = threadIdx.x; i < IDIM; i += blockDim.x) {
        __nv_bfloat16 hh, ll; split_bf(src[i], hh, ll);
        size_t off = BW_OFF(n, i);
        *(__nv_bfloat16*)((char*)g_Bwh + off) = hh;
        *(__nv_bfloat16*)((char*)g_Bwl + off) = ll;
    }
    if (threadIdx.x == 0) g_b0r[n] = b0[g * HH + h];
}

__global__ void repack_w0(const float* __restrict__ Uh0, const float* __restrict__ Vc0) {
    int n = blockIdx.x, g = n & 3, h = n >> 2;
    const float* u = Uh0 + (size_t)(g * HH + h) * HH;
    for (int k = threadIdx.x; k < HH; k += blockDim.x) {
        __nv_bfloat16 hh, ll; split_bf(u[k], hh, ll);
        size_t off = W0_OFF(n, k);
        *(__nv_bfloat16*)((char*)g_W0h + off) = hh;
        *(__nv_bfloat16*)((char*)g_W0l + off) = ll;
    }
    int vg = (g == 0) ? 0 : (g == 1) ? 1 : (g == 3) ? 2 : -1;
    const float* v = (vg >= 0) ? (Vc0 + (size_t)(vg * HH + h) * HH) : 0;
    for (int k = threadIdx.x; k < HH; k += blockDim.x) {
        float val = (vg >= 0) ? v[k] : 0.0f;
        __nv_bfloat16 hh, ll; split_bf(val, hh, ll);
        size_t off = W0_OFF(n, HH + k);
        *(__nv_bfloat16*)((char*)g_W0h + off) = hh;
        *(__nv_bfloat16*)((char*)g_W0l + off) = ll;
    }
}

__global__ void repack_w1(const float* __restrict__ Wx1, const float* __restrict__ Uh1,
                          const float* __restrict__ Vc1, const float* __restrict__ b1) {
    int n = blockIdx.x, g = n & 3, h = n >> 2;
    const float* wx = Wx1 + (size_t)(g * HH + h) * HH;
    const float* uh = Uh1 + (size_t)(g * HH + h) * HH;
    for (int k = threadIdx.x; k < HH; k += blockDim.x) {
        __nv_bfloat16 hh, ll;
        split_bf(wx[k], hh, ll);
        size_t off = W1_OFF(n, k);
        *(__nv_bfloat16*)((char*)g_W1h + off) = hh;
        *(__nv_bfloat16*)((char*)g_W1l + off) = ll;
        split_bf(uh[k], hh, ll);
        off = W1_OFF(n, HH + k);
        *(__nv_bfloat16*)((char*)g_W1h + off) = hh;
        *(__nv_bfloat16*)((char*)g_W1l + off) = ll;
    }
    int vg = (g == 0) ? 0 : (g == 1) ? 1 : (g == 3) ? 2 : -1;
    const float* v = (vg >= 0) ? (Vc1 + (size_t)(vg * HH + h) * HH) : 0;
    for (int k = threadIdx.x; k < HH; k += blockDim.x) {
        float val = (vg >= 0) ? v[k] : 0.0f;
        __nv_bfloat16 hh, ll; split_bf(val, hh, ll);
        size_t off = W1_OFF(n, 2 * HH + k);
        *(__nv_bfloat16*)((char*)g_W1h + off) = hh;
        *(__nv_bfloat16*)((char*)g_W1l + off) = ll;
    }
    if (threadIdx.x == 0) g_b1r[n] = b1[g * HH + h];
}

__global__ void init_state(const float* __restrict__ h0, const float* __restrict__ c0) {
    int idx = blockIdx.x * blockDim.x + threadIdx.x;
    if (idx == 0) g_bar = 0u;
    int b = idx >> 10, h = idx & 1023;
    __nv_bfloat16 hh, ll; float v; size_t off;
    v = h0[b * HH + h]; split_bf(v, hh, ll);
    off = ST_OFF(h, b);
    *(__nv_bfloat16*)((char*)g_S0h + off) = hh; *(__nv_bfloat16*)((char*)g_S0l + off) = ll;
    v = c0[b * HH + h]; g_C0[idx] = v; split_bf(v, hh, ll);
    off = ST_OFF(HH + h, b);
    *(__nv_bfloat16*)((char*)g_S0h + off) = hh; *(__nv_bfloat16*)((char*)g_S0l + off) = ll;
    v = h0[BB * HH + b * HH + h]; split_bf(v, hh, ll);
    off = ST_OFF(HH + h, b);
    *(__nv_bfloat16*)((char*)g_S1h + off) = hh; *(__nv_bfloat16*)((char*)g_S1l + off) = ll;
    v = c0[BB * HH + b * HH + h]; g_C1[idx] = v; split_bf(v, hh, ll);
    off = ST_OFF(2 * HH + h, b);
    *(__nv_bfloat16*)((char*)g_S1h + off) = hh; *(__nv_bfloat16*)((char*)g_S1l + off) = ll;
    off = ST_OFF(h, b);
    *(__nv_bfloat16*)((char*)g_S1h + off) = __float2bfloat16(0.0f);
    *(__nv_bfloat16*)((char*)g_S1l + off) = __float2bfloat16(0.0f);
}

// ---- phase A: bf16 3-term, CTA 128x128, 64 chunks of k64; 2 stages (R7 verbatim) ----
#define XZ_STAGE 65536u
__global__ __launch_bounds__(256) void gemm_xz_mma() {
    extern __shared__ __align__(128) char dsm[];
    __shared__ __align__(8) unsigned long long mbars[2];
    const int tid = threadIdx.x, w = tid >> 5, l = tid & 31;
    const int wm = w & 3, wn = w >> 2;
    const int m0 = blockIdx.y * 128, n0 = blockIdx.x * 128;
    const uint32_t sb = smem_u32(dsm), mb0 = smem_u32(mbars);
    if (tid == 0) { mbar_init(mb0, 1); mbar_init(mb0 + 8, 1); }
    __syncthreads();
    const char* Ah = (const char*)g_Axh + ((size_t)blockIdx.y * 64) * 16384;
    const char* Al = (const char*)g_Axl + ((size_t)blockIdx.y * 64) * 16384;
    const char* Bh = (const char*)g_Bwh + ((size_t)blockIdx.x * 64) * 16384;
    const char* Bl = (const char*)g_Bwl + ((size_t)blockIdx.x * 64) * 16384;
    auto issue = [&](int kc) {
        int st = kc & 1;
        uint32_t d = sb + st * XZ_STAGE, mb = mb0 + st * 8;
        mbar_expect(mb, XZ_STAGE);
        bulk_cp(d,         Ah + (size_t)kc * 16384, 16384, mb);
        bulk_cp(d + 16384, Al + (size_t)kc * 16384, 16384, mb);
        bulk_cp(d + 32768, Bh + (size_t)kc * 16384, 16384, mb);
        bulk_cp(d + 49152, Bl + (size_t)kc * 16384, 16384, mb);
    };
    if (tid == 0) { issue(0); issue(1); }

    float acc[2][8][4];
#pragma unroll
    for (int a = 0; a < 2; a++)
#pragma unroll
        for (int b = 0; b < 8; b++)
#pragma unroll
            for (int c = 0; c < 4; c++) acc[a][b][c] = 0.0f;

    unsigned pst[2] = {0, 0};
    for (int kc = 0; kc < 64; kc++) {
        const int st = kc & 1;
        const uint32_t stb = sb + st * XZ_STAGE;
        mbar_wait(mb0 + st * 8, pst[st] & 1); pst[st]++;
#pragma unroll
        for (int ks = 0; ks < 4; ks++) {
            const int kb = ks * 32;
            uint32_t ah[2][4], al[2][4];
#pragma unroll
            for (int mt = 0; mt < 2; mt++) {
                int row = wm * 32 + mt * 16 + (l & 15);
                uint32_t ra = stb + (uint32_t)(row * 128 + ((kb + ((l >> 4) << 4)) ^ ((row & 7) << 4)));
                ldsm_x4(ah[mt], ra);
                ldsm_x4(al[mt], ra + 16384);
            }
#pragma unroll
            for (int nt = 0; nt < 8; nt++) {
                int row = wn * 64 + nt * 8 + (l & 7);
                uint32_t rb = stb + 32768 +
                    (uint32_t)(row * 128 + ((kb + (((l >> 3) & 1) << 4)) ^ ((row & 7) << 4)));
                uint32_t bh[2], bl[2];
                ldsm_x2(bh, rb);
                ldsm_x2(bl, rb + 16384);
#pragma unroll
                for (int mt = 0; mt < 2; mt++) {
                    mma_bf16(acc[mt][nt], ah[mt], bh);
                    mma_bf16(acc[mt][nt], ah[mt], bl);
                    mma_bf16(acc[mt][nt], al[mt], bh);
                }
            }
        }
        __syncthreads();
        if (tid == 0 && kc + 2 < 64) issue(kc + 2);
    }

    const int r0 = l >> 2, cp2 = (l & 3) * 2;
#pragma unroll
    for (int mt = 0; mt < 2; mt++)
#pragma unroll
        for (int half = 0; half < 2; half++) {
            int gm = m0 + wm * 32 + mt * 16 + r0 + half * 8;
            int t = gm & (TT - 1), b = gm >> 7;
            float* dst = g_XZ0 + ((size_t)(t * BB + b) << 12);
#pragma unroll
            for (int nt = 0; nt < 8; nt++) {
                int gc = n0 + wn * 64 + nt * 8 + cp2;
                float2 v;
                v.x = acc[mt][nt][half * 2 + 0] + g_b0r[gc];
                v.y = acc[mt][nt][half * 2 + 1] + g_b0r[gc + 1];
                *(float2*)(dst + gc) = v;
            }
        }
}

// ---- persistent loop: 512 threads, k-chunk 128, 2 stages of 96KB ----
#define LP_STAGE 98304u
#define LOOP_SMEM (2u * LP_STAGE)
template <int WHICH>
__device__ __forceinline__ void issueLP(int nblk, int kseg, int kc, uint32_t sb, uint32_t mb0) {
    constexpr int NKC64 = (WHICH ? K1 : K0) / 64;
    constexpr int NC    = NKC64 / 2 / KSPLIT;            // 4 or 6 (k128 chunks)
    const char* Sh = (const char*)(WHICH ? g_S1h : g_S0h);
    const char* Sl = (const char*)(WHICH ? g_S1l : g_S0l);
    const char* Wh = (const char*)(WHICH ? g_W1h : g_W0h);
    const char* Wl = (const char*)(WHICH ? g_W1l : g_W0l);
    const int kcA = (kseg * NC + kc) * 2;                // in kc64 units
    int st = kc & 1;
    uint32_t d = sb + st * LP_STAGE, mb = mb0 + st * 8;
    mbar_expect(mb, LP_STAGE);
    bulk_cp(d,         Sh + (size_t)kcA * 8192, 16384, mb);
    bulk_cp(d + 16384, Sl + (size_t)kcA * 8192, 16384, mb);
    bulk_cp(d + 32768, Wh + ((size_t)nblk * NKC64 + kcA) * 16384, 32768, mb);
    bulk_cp(d + 65536, Wl + ((size_t)nblk * NKC64 + kcA) * 16384, 32768, mb);
}

template <int WHICH>
__device__ __forceinline__ void gemm_phase(int cta, int tid, uint32_t sb, uint32_t mb0, unsigned* uses) {
    constexpr int NC = ((WHICH ? K1 : K0) / 128) / KSPLIT;   // 4 or 6
    const int w = tid >> 5, l = tid & 31;
    const int wm = w & 3, wn = w >> 2;                   // 16 warps: 4 m x 4 n
    const int nblk = cta & 31, kseg = cta >> 5;

    if (tid == 0) { issueLP<WHICH>(nblk, kseg, 0, sb, mb0); issueLP<WHICH>(nblk, kseg, 1, sb, mb0); }

    float acc[4][4];
#pragma unroll
    for (int b = 0; b < 4; b++)
#pragma unroll
        for (int c = 0; c < 4; c++) acc[b][c] = 0.0f;

    for (int kc = 0; kc < NC; kc++) {
        const int st = kc & 1;
        const uint32_t stb = sb + st * LP_STAGE;
        mbar_wait(mb0 + st * 8, uses[st] & 1); uses[st]++;
#pragma unroll
        for (int ks = 0; ks < 8; ks++) {
            const int kcs = ks >> 2, kb = (ks & 3) * 32;
            uint32_t ah[4], al[4];
            int arow = wm * 16 + (l & 15);
            uint32_t ra = stb + kcs * 8192 +
                (uint32_t)(arow * 128 + ((kb + ((l >> 4) << 4)) ^ ((arow & 7) << 4)));
            ldsm_x4(ah, ra);
            ldsm_x4(al, ra + 16384);
#pragma unroll
            for (int nt = 0; nt < 4; nt++) {
                int brow = wn * 32 + nt * 8 + (l & 7);
                uint32_t rb = stb + 32768 + kcs * 16384 +
                    (uint32_t)(brow * 128 + ((kb + (((l >> 3) & 1) << 4)) ^ ((brow & 7) << 4)));
                uint32_t bh[2], bl[2];
                ldsm_x2(bh, rb);
                ldsm_x2(bl, rb + 32768);
                mma_bf16(acc[nt], ah, bh);
                mma_bf16(acc[nt], ah, bl);
                mma_bf16(acc[nt], al, bh);
            }
        }
        __syncthreads();
        if (tid == 0 && kc + 2 < NC) issueLP<WHICH>(nblk, kseg, kc + 2, sb, mb0);
    }

    float* dst = g_P[kseg];
    const int r0 = l >> 2, cp2 = (l & 3) * 2;
#pragma unroll
    for (int half = 0; half < 2; half++) {
        int b = wm * 16 + r0 + half * 8;
#pragma unroll
        for (int nt = 0; nt < 4; nt++) {
            int gc = nblk * 128 + wn * 32 + nt * 8 + cp2;
            *(float2*)(dst + ((size_t)b << 12) + gc) =
                make_float2(acc[nt][half * 2 + 0], acc[nt][half * 2 + 1]);
        }
    }
}

__global__ __launch_bounds__(512) void rnn_loop(float* __restrict__ out) {
    extern __shared__ __align__(128) char dsm[];
    __shared__ __align__(8) unsigned long long mbars[2];
    const int cta = blockIdx.x, tid = threadIdx.x;
    const uint32_t sb = smem_u32(dsm);
    const uint32_t mb0 = smem_u32(mbars);
    if (tid == 0) { mbar_init(mb0, 1); mbar_init(mb0 + 8, 1); }
    __syncthreads();

    const int idx = cta * 512 + tid;         // one (b,h) cell per thread
    const int b = idx >> 10, h = idx & 1023;
    float cA = g_C0[idx];
    float cB = g_C1[idx];
    float* hn_base = out + (size_t)BB * TT * HH;
    float* cn_base = hn_base + 2 * BB * HH;
    unsigned int seq = 0;
    unsigned uses[2] = {0, 0};

    const int nb = h << 2;
    for (int t = 0; t < TT; t++) {
        gemm_phase<0>(cta, tid, sb, mb0, uses);
        grid_sync(++seq * GRID_N);

        { // epi0
            float4 z = *(const float4*)&g_XZ0[((size_t)(t * BB + b) << 12) + nb];
#pragma unroll
            for (int ks = 0; ks < KSPLIT; ks++) {
                float4 pp = __ldcg((const float4*)&g_P[ks][((size_t)b << 12) + nb]);
                z.x += pp.x; z.y += pp.y; z.z += pp.z; z.w += pp.w;
            }
            float ig = sig_(z.x), fg = sig_(z.y), gg = tanhf(z.z), og = sig_(z.w);
            float cn = fg * cA + ig * gg;
            float hn = og * tanhf(cn);
            cA = cn;
            __nv_bfloat16 hh, ll, ch, cl;
            split_bf(hn, hh, ll); split_bf(cn, ch, cl);
            size_t off = ST_OFF(h, b);
            *(__nv_bfloat16*)((char*)g_S0h + off) = hh; *(__nv_bfloat16*)((char*)g_S0l + off) = ll;
            *(__nv_bfloat16*)((char*)g_S1h + off) = hh; *(__nv_bfloat16*)((char*)g_S1l + off) = ll;
            off = ST_OFF(HH + h, b);
            *(__nv_bfloat16*)((char*)g_S0h + off) = ch; *(__nv_bfloat16*)((char*)g_S0l + off) = cl;
            if (t == TT - 1) { hn_base[b * HH + h] = hn; cn_base[b * HH + h] = cn; }
        }
        grid_sync(++seq * GRID_N);

        gemm_phase<1>(cta, tid, sb, mb0, uses);
        grid_sync(++seq * GRID_N);

        { // epi1
            float4 z = *(const float4*)&g_b1r[nb];
#pragma unroll
            for (int ks = 0; ks < KSPLIT; ks++) {
                float4 pp = __ldcg((const float4*)&g_P[ks][((size_t)b << 12) + nb]);
                z.x += pp.x; z.y += pp.y; z.z += pp.z; z.w += pp.w;
            }
            float ig = sig_(z.x), fg = sig_(z.y), gg = tanhf(z.z), og = sig_(z.w);
            float cn = fg * cB + ig * gg;
            float hn = og * tanhf(cn);
            cB = cn;
            __nv_bfloat16 hh, ll, ch, cl;
            split_bf(hn, hh, ll); split_bf(cn, ch, cl);
            size_t off = ST_OFF(HH + h, b);
            *(__nv_bfloat16*)((char*)g_S1h + off) = hh; *(__nv_bfloat16*)((char*)g_S1l + off) = ll;
            off = ST_OFF(2 * HH + h, b);
            *(__nv_bfloat16*)((char*)g_S1h + off) = ch; *(__nv_bfloat16*)((char*)g_S1l + off) = cl;
            out[((size_t)b * TT + t) * HH + h] = hn;
            if (t == TT - 1) {
                hn_base[BB * HH + b * HH + h] = hn;
                cn_base[BB * HH + b * HH + h] = cn;
            }
        }
        grid_sync(++seq * GRID_N);
    }
}

extern "C" void kernel_launch(void* const* d_in, const int* in_sizes, int n_in,
                              void* d_out, int out_size) {
    (void)in_sizes; (void)n_in; (void)out_size;
    const float* x   = (const float*)d_in[0];
    const float* h0  = (const float*)d_in[1];
    const float* c0  = (const float*)d_in[2];
    const float* Wx0 = (const float*)d_in[3];
    const float* Uh0 = (const float*)d_in[4];
    const float* Vc0 = (const float*)d_in[5];
    const float* b0  = (const float*)d_in[6];
    const float* Wx1 = (const float*)d_in[7];
    const float* Uh1 = (const float*)d_in[8];
    const float* Vc1 = (const float*)d_in[9];
    const float* b1  = (const float*)d_in[10];
    float* out = (float*)d_out;

    cudaFuncSetAttribute(gemm_xz_mma, cudaFuncAttributeMaxDynamicSharedMemorySize, 2 * XZ_STAGE);
    cudaFuncSetAttribute(rnn_loop,    cudaFuncAttributeMaxDynamicSharedMemorySize, LOOP_SMEM);

    conv_x     <<<(BB * TT * IDIM) / (4 * 256), 256>>>(x);
    repack_wx0b<<<FOURH, 256>>>(Wx0, b0);
    repack_w0  <<<FOURH, 256>>>(Uh0, Vc0);
    repack_w1  <<<FOURH, 256>>>(Wx1, Uh1, Vc1, b1);
    init_state <<<(BB * HH) / 256, 256>>>(h0, c0);

    gemm_xz_mma<<<dim3(FOURH / 128, (BB * TT) / 128), 256, 2 * XZ_STAGE>>>();

    rnn_loop<<<GRID_N, 512, LOOP_SMEM>>>(out);
}

// round 13
// speedup vs baseline: 1.3712x; 1.3498x over previous
#include <cuda_runtime.h>
#include <cuda_fp16.h>
#include <math.h>
#include <stdint.h>

#define BB 64
#define TT 128
#define IDIM 4096
#define HH 1024
#define FOURH 4096
#define K0 2048
#define K1 3072
#define KSPLIT 4
#define GRID_N 128

// ---- scratch: chunk-tiled, swizzle pre-baked (16B group g of row r at g^(r&7)) ----
// fp16 2-term scheme: A operands split hi/lo fp16; weights single-plane fp16.
__device__ __align__(128) float g_XZ0[(size_t)TT * BB * FOURH];
__device__ __align__(128) __half g_Axh[(size_t)BB * TT * IDIM];
__device__ __align__(128) __half g_Axl[(size_t)BB * TT * IDIM];
__device__ __align__(128) __half g_Bw[(size_t)FOURH * IDIM];
__device__ __align__(128) __half g_W0[(size_t)FOURH * K0];
__device__ __align__(128) __half g_W1[(size_t)FOURH * K1];
__device__ float g_b0r[FOURH];
__device__ float g_b1r[FOURH];
__device__ __align__(128) __half g_S0h[BB * K0];
__device__ __align__(128) __half g_S0l[BB * K0];
__device__ __align__(128) __half g_S1h[BB * K1];
__device__ __align__(128) __half g_S1l[BB * K1];
__device__ float g_C0[BB * HH];
__device__ float g_C1[BB * HH];
__device__ float g_P[KSPLIT][BB * FOURH];
__device__ unsigned int g_bar;

#define AX_OFF(r,k) ( (((size_t)(((r)>>7)*64+((k)>>6)))<<14) + (size_t)(((r)&127)<<7) + (size_t)(((((k)&63)*2)^(((r)&7)<<4))) )
#define BW_OFF(n,k) AX_OFF(n,k)
#define W0_OFF(n,k) ( (((size_t)(((n)>>7)*32+((k)>>6)))<<14) + (size_t)(((n)&127)<<7) + (size_t)(((((k)&63)*2)^(((n)&7)<<4))) )
#define W1_OFF(n,k) ( (((size_t)(((n)>>7)*48+((k)>>6)))<<14) + (size_t)(((n)&127)<<7) + (size_t)(((((k)&63)*2)^(((n)&7)<<4))) )
#define ST_OFF(k,b) ( (((size_t)((k)>>6))<<13) + (size_t)((b)<<7) + (size_t)(((((k)&63)*2)^(((b)&7)<<4))) )

// ---- PTX helpers ----
__device__ __forceinline__ uint32_t smem_u32(const void* p) {
    uint32_t a;
    asm("{ .reg .u64 t; cvta.to.shared.u64 t, %1; cvt.u32.u64 %0, t; }" : "=r"(a) : "l"(p));
    return a;
}
__device__ __forceinline__ void mbar_init(uint32_t m, uint32_t c) {
    asm volatile("mbarrier.init.shared.b64 [%0], %1;" :: "r"(m), "r"(c) : "memory");
}
__device__ __forceinline__ void mbar_expect(uint32_t m, uint32_t b) {
    asm volatile("mbarrier.arrive.expect_tx.shared.b64 _, [%0], %1;" :: "r"(m), "r"(b) : "memory");
}
__device__ __forceinline__ void mbar_wait(uint32_t m, uint32_t par) {
    asm volatile(
        "{\n\t.reg .pred P;\nWL%=:\n\t"
        "mbarrier.try_wait.parity.shared.b64 P, [%0], %1;\n\t"
        "@P bra.uni WD%=;\n\tbra.uni WL%=;\nWD%=:\n\t}"
        :: "r"(m), "r"(par) : "memory");
}
__device__ __forceinline__ void bulk_cp(uint32_t d, const void* s, uint32_t b, uint32_t m) {
    asm volatile("cp.async.bulk.shared::cta.global.mbarrier::complete_tx::bytes [%0], [%1], %2, [%3];"
                 :: "r"(d), "l"(s), "r"(b), "r"(m) : "memory");
}
__device__ __forceinline__ void ldsm_x4(uint32_t* r, uint32_t a) {
    asm volatile("ldmatrix.sync.aligned.m8n8.x4.shared.b16 {%0,%1,%2,%3}, [%4];"
                 : "=r"(r[0]), "=r"(r[1]), "=r"(r[2]), "=r"(r[3]) : "r"(a));
}
__device__ __forceinline__ void ldsm_x2(uint32_t* r, uint32_t a) {
    asm volatile("ldmatrix.sync.aligned.m8n8.x2.shared.b16 {%0,%1}, [%2];"
                 : "=r"(r[0]), "=r"(r[1]) : "r"(a));
}
__device__ __forceinline__ void mma_f16(float* d, const uint32_t* a, const uint32_t* b) {
    asm volatile("mma.sync.aligned.m16n8k16.row.col.f32.f16.f16.f32 "
        "{%0,%1,%2,%3}, {%4,%5,%6,%7}, {%8,%9}, {%0,%1,%2,%3};"
        : "+f"(d[0]), "+f"(d[1]), "+f"(d[2]), "+f"(d[3])
        : "r"(a[0]), "r"(a[1]), "r"(a[2]), "r"(a[3]), "r"(b[0]), "r"(b[1]));
}
__device__ __forceinline__ void split_h(float v, __half& h, __half& l) {
    h = __float2half_rn(v);
    l = __float2half_rn(v - __half2float(h));
}
__device__ __forceinline__ uint32_t pack_h2(__half a, __half b) {
    union { __half h[2]; uint32_t u; } t; t.h[0] = a; t.h[1] = b; return t.u;
}
__device__ __forceinline__ float sig_(float z) { return 1.0f / (1.0f + expf(-z)); }

__device__ __forceinline__ void grid_sync(unsigned int target) {
    asm volatile("fence.proxy.async;" ::: "memory");
    __syncthreads();
    if (threadIdx.x == 0) {
        __threadfence();
        atomicAdd(&g_bar, 1u);
        while (__ldcg(&g_bar) < target) __nanosleep(32);
        __threadfence();
    }
    __syncthreads();
}

// ---- prep kernels ----
__global__ void conv_x(const float* __restrict__ x) {
    size_t i0 = ((size_t)blockIdx.x * 256 + threadIdx.x) * 4;
    float4 v = *(const float4*)(x + i0);
    union { __half b[4]; uint2 u; } ph, pl;
    split_h(v.x, ph.b[0], pl.b[0]); split_h(v.y, ph.b[1], pl.b[1]);
    split_h(v.z, ph.b[2], pl.b[2]); split_h(v.w, ph.b[3], pl.b[3]);
    size_t off = AX_OFF((int)(i0 >> 12), (int)(i0 & 4095));
    *(uint2*)((char*)g_Axh + off) = ph.u;
    *(uint2*)((char*)g_Axl + off) = pl.u;
}

__global__ void repack_wx0b(const float* __restrict__ Wx0, const float* __restrict__ b0) {
    int n = blockIdx.x, g = n & 3, h = n >> 2;
    const float* src = Wx0 + (size_t)(g * HH + h) * IDIM;
    for (int i = threadIdx.x; i < IDIM; i += blockDim.x)
        *(__half*)((char*)g_Bw + BW_OFF(n, i)) = __float2half_rn(src[i]);
    if (threadIdx.x == 0) g_b0r[n] = b0[g * HH + h];
}

__global__ void repack_w0(const float* __restrict__ Uh0, const float* __restrict__ Vc0) {
    int n = blockIdx.x, g = n & 3, h = n >> 2;
    const float* u = Uh0 + (size_t)(g * HH + h) * HH;
    for (int k = threadIdx.x; k < HH; k += blockDim.x)
        *(__half*)((char*)g_W0 + W0_OFF(n, k)) = __float2half_rn(u[k]);
    int vg = (g == 0) ? 0 : (g == 1) ? 1 : (g == 3) ? 2 : -1;
    const float* v = (vg >= 0) ? (Vc0 + (size_t)(vg * HH + h) * HH) : 0;
    for (int k = threadIdx.x; k < HH; k += blockDim.x) {
        float val = (vg >= 0) ? v[k] : 0.0f;
        *(__half*)((char*)g_W0 + W0_OFF(n, HH + k)) = __float2half_rn(val);
    }
}

__global__ void repack_w1(const float* __restrict__ Wx1, const float* __restrict__ Uh1,
                          const float* __restrict__ Vc1, const float* __restrict__ b1) {
    int n = blockIdx.x, g = n & 3, h = n >> 2;
    const float* wx = Wx1 + (size_t)(g * HH + h) * HH;
    const float* uh = Uh1 + (size_t)(g * HH + h) * HH;
    for (int k = threadIdx.x; k < HH; k += blockDim.x) {
        *(__half*)((char*)g_W1 + W1_OFF(n, k))      = __float2half_rn(wx[k]);
        *(__half*)((char*)g_W1 + W1_OFF(n, HH + k)) = __float2half_rn(uh[k]);
    }
    int vg = (g == 0) ? 0 : (g == 1) ? 1 : (g == 3) ? 2 : -1;
    const float* v = (vg >= 0) ? (Vc1 + (size_t)(vg * HH + h) * HH) : 0;
    for (int k = threadIdx.x; k < HH; k += blockDim.x) {
        float val = (vg >= 0) ? v[k] : 0.0f;
        *(__half*)((char*)g_W1 + W1_OFF(n, 2 * HH + k)) = __float2half_rn(val);
    }
    if (threadIdx.x == 0) g_b1r[n] = b1[g * HH + h];
}

__global__ void init_state(const float* __restrict__ h0, const float* __restrict__ c0) {
    int idx = blockIdx.x * blockDim.x + threadIdx.x;
    if (idx == 0) g_bar = 0u;
    int b = idx >> 10, h = idx & 1023;
    __half hh, ll; float v; size_t off;
    v = h0[b * HH + h]; split_h(v, hh, ll);
    off = ST_OFF(h, b);
    *(__half*)((char*)g_S0h + off) = hh; *(__half*)((char*)g_S0l + off) = ll;
    v = c0[b * HH + h]; g_C0[idx] = v; split_h(v, hh, ll);
    off = ST_OFF(HH + h, b);
    *(__half*)((char*)g_S0h + off) = hh; *(__half*)((char*)g_S0l + off) = ll;
    v = h0[BB * HH + b * HH + h]; split_h(v, hh, ll);
    off = ST_OFF(HH + h, b);
    *(__half*)((char*)g_S1h + off) = hh; *(__half*)((char*)g_S1l + off) = ll;
    v = c0[BB * HH + b * HH + h]; g_C1[idx] = v; split_h(v, hh, ll);
    off = ST_OFF(2 * HH + h, b);
    *(__half*)((char*)g_S1h + off) = hh; *(__half*)((char*)g_S1l + off) = ll;
    off = ST_OFF(h, b);
    *(__half*)((char*)g_S1h + off) = __float2half(0.0f);
    *(__half*)((char*)g_S1l + off) = __float2half(0.0f);
}

// ---- phase A: fp16 2-term, CTA 128x128, 64 chunks of k64; stage 48KB x2 ----
#define XZ_STAGE 49152u
__global__ __launch_bounds__(256) void gemm_xz_mma() {
    extern __shared__ __align__(128) char dsm[];
    __shared__ __align__(8) unsigned long long mbars[2];
    const int tid = threadIdx.x, w = tid >> 5, l = tid & 31;
    const int wm = w & 3, wn = w >> 2;
    const int m0 = blockIdx.y * 128, n0 = blockIdx.x * 128;
    const uint32_t sb = smem_u32(dsm), mb0 = smem_u32(mbars);
    if (tid == 0) { mbar_init(mb0, 1); mbar_init(mb0 + 8, 1); }
    __syncthreads();
    const char* Ah = (const char*)g_Axh + ((size_t)blockIdx.y * 64) * 16384;
    const char* Al = (const char*)g_Axl + ((size_t)blockIdx.y * 64) * 16384;
    const char* Bw = (const char*)g_Bw + ((size_t)blockIdx.x * 64) * 16384;
    auto issue = [&](int kc) {
        int st = kc & 1;
        uint32_t d = sb + st * XZ_STAGE, mb = mb0 + st * 8;
        mbar_expect(mb, XZ_STAGE);
        bulk_cp(d,         Ah + (size_t)kc * 16384, 16384, mb);
        bulk_cp(d + 16384, Al + (size_t)kc * 16384, 16384, mb);
        bulk_cp(d + 32768, Bw + (size_t)kc * 16384, 16384, mb);
    };
    if (tid == 0) { issue(0); issue(1); }

    float acc[2][8][4];
#pragma unroll
    for (int a = 0; a < 2; a++)
#pragma unroll
        for (int b = 0; b < 8; b++)
#pragma unroll
            for (int c = 0; c < 4; c++) acc[a][b][c] = 0.0f;

    unsigned pst[2] = {0, 0};
    for (int kc = 0; kc < 64; kc++) {
        const int st = kc & 1;
        const uint32_t stb = sb + st * XZ_STAGE;
        mbar_wait(mb0 + st * 8, pst[st] & 1); pst[st]++;
#pragma unroll
        for (int ks = 0; ks < 4; ks++) {
            const int kb = ks * 32;
            uint32_t ah[2][4], al[2][4];
#pragma unroll
            for (int mt = 0; mt < 2; mt++) {
                int row = wm * 32 + mt * 16 + (l & 15);
                uint32_t ra = stb + (uint32_t)(row * 128 + ((kb + ((l >> 4) << 4)) ^ ((row & 7) << 4)));
                ldsm_x4(ah[mt], ra);
                ldsm_x4(al[mt], ra + 16384);
            }
#pragma unroll
            for (int nt = 0; nt < 8; nt++) {
                int row = wn * 64 + nt * 8 + (l & 7);
                uint32_t rb = stb + 32768 +
                    (uint32_t)(row * 128 + ((kb + (((l >> 3) & 1) << 4)) ^ ((row & 7) << 4)));
                uint32_t bw[2];
                ldsm_x2(bw, rb);
#pragma unroll
                for (int mt = 0; mt < 2; mt++) {
                    mma_f16(acc[mt][nt], ah[mt], bw);
                    mma_f16(acc[mt][nt], al[mt], bw);
                }
            }
        }
        __syncthreads();
        if (tid == 0 && kc + 2 < 64) issue(kc + 2);
    }

    const int r0 = l >> 2, cp2 = (l & 3) * 2;
#pragma unroll
    for (int mt = 0; mt < 2; mt++)
#pragma unroll
        for (int half = 0; half < 2; half++) {
            int gm = m0 + wm * 32 + mt * 16 + r0 + half * 8;
            int t = gm & (TT - 1), b = gm >> 7;
            float* dst = g_XZ0 + ((size_t)(t * BB + b) << 12);
#pragma unroll
            for (int nt = 0; nt < 8; nt++) {
                int gc = n0 + wn * 64 + nt * 8 + cp2;
                float2 v;
                v.x = acc[mt][nt][half * 2 + 0] + g_b0r[gc];
                v.y = acc[mt][nt][half * 2 + 1] + g_b0r[gc + 1];
                *(float2*)(dst + gc) = v;
            }
        }
}

// ---- persistent loop: fp16 2-term; stage 32KB x2 ----
#define LP_STAGE 32768u
#define LOOP_SMEM (2u * LP_STAGE)
template <int WHICH>
__device__ __forceinline__ void issueLP(int nblk, int kseg, int kc, uint32_t sb, uint32_t mb0) {
    constexpr int NKC = (WHICH ? K1 : K0) / 64;
    constexpr int NC  = NKC / KSPLIT;
    const char* Sh = (const char*)(WHICH ? g_S1h : g_S0h);
    const char* Sl = (const char*)(WHICH ? g_S1l : g_S0l);
    const char* Wp = (const char*)(WHICH ? g_W1 : g_W0);
    const int kcA = kseg * NC + kc;
    int st = kc & 1;
    uint32_t d = sb + st * LP_STAGE, mb = mb0 + st * 8;
    mbar_expect(mb, LP_STAGE);
    bulk_cp(d,         Sh + (size_t)kcA * 8192, 8192, mb);
    bulk_cp(d + 8192,  Sl + (size_t)kcA * 8192, 8192, mb);
    bulk_cp(d + 16384, Wp + ((size_t)nblk * NKC + kcA) * 16384, 16384, mb);
}

template <int WHICH>
__device__ __forceinline__ void gemm_phase(int cta, int tid, uint32_t sb, uint32_t mb0, unsigned* uses) {
    constexpr int NC = ((WHICH ? K1 : K0) / 64) / KSPLIT;   // 8 or 12
    const int w = tid >> 5, l = tid & 31;
    const int wm = w & 3, wn = w >> 2;
    const int nblk = cta & 31, kseg = cta >> 5;

    if (tid == 0) { issueLP<WHICH>(nblk, kseg, 0, sb, mb0); issueLP<WHICH>(nblk, kseg, 1, sb, mb0); }

    float acc[8][4];
#pragma unroll
    for (int b = 0; b < 8; b++)
#pragma unroll
        for (int c = 0; c < 4; c++) acc[b][c] = 0.0f;

    for (int kc = 0; kc < NC; kc++) {
        const int st = kc & 1;
        const uint32_t stb = sb + st * LP_STAGE;
        mbar_wait(mb0 + st * 8, uses[st] & 1); uses[st]++;
#pragma unroll
        for (int ks = 0; ks < 4; ks++) {
            const int kb = ks * 32;
            uint32_t ah[4], al[4];
            int arow = wm * 16 + (l & 15);
            uint32_t ra = stb + (uint32_t)(arow * 128 + ((kb + ((l >> 4) << 4)) ^ ((arow & 7) << 4)));
            ldsm_x4(ah, ra);
            ldsm_x4(al, ra + 8192);
#pragma unroll
            for (int nt = 0; nt < 8; nt++) {
                int brow = wn * 64 + nt * 8 + (l & 7);
                uint32_t rb = stb + 16384 +
                    (uint32_t)(brow * 128 + ((kb + (((l >> 3) & 1) << 4)) ^ ((brow & 7) << 4)));
                uint32_t bw[2];
                ldsm_x2(bw, rb);
                mma_f16(acc[nt], ah, bw);
                mma_f16(acc[nt], al, bw);
            }
        }
        __syncthreads();
        if (tid == 0 && kc + 2 < NC) issueLP<WHICH>(nblk, kseg, kc + 2, sb, mb0);
    }

    float* dst = g_P[kseg];
    const int r0 = l >> 2, cp2 = (l & 3) * 2;
#pragma unroll
    for (int half = 0; half < 2; half++) {
        int b = wm * 16 + r0 + half * 8;
#pragma unroll
        for (int nt = 0; nt < 8; nt++) {
            int gc = nblk * 128 + wn * 64 + nt * 8 + cp2;
            *(float2*)(dst + ((size_t)b << 12) + gc) =
                make_float2(acc[nt][half * 2 + 0], acc[nt][half * 2 + 1]);
        }
    }
}

__global__ __launch_bounds__(256) void rnn_loop(float* __restrict__ out) {
    extern __shared__ __align__(128) char dsm[];
    __shared__ __align__(8) unsigned long long mbars[2];
    const int cta = blockIdx.x, tid = threadIdx.x;
    const uint32_t sb = smem_u32(dsm);
    const uint32_t mb0 = smem_u32(mbars);
    if (tid == 0) { mbar_init(mb0, 1); mbar_init(mb0 + 8, 1); }
    __syncthreads();

    const int idx0 = (cta * 256 + tid) * 2;     // two cells (same b, consecutive h)
    const int b = idx0 >> 10, h0i = idx0 & 1023;
    float cA[2] = { g_C0[idx0], g_C0[idx0 + 1] };
    float cB[2] = { g_C1[idx0], g_C1[idx0 + 1] };
    float* hn_base = out + (size_t)BB * TT * HH;
    float* cn_base = hn_base + 2 * BB * HH;
    unsigned int seq = 0;
    unsigned uses[2] = {0, 0};

    for (int t = 0; t < TT; t++) {
        gemm_phase<0>(cta, tid, sb, mb0, uses);
        grid_sync(++seq * GRID_N);

        { // epi0
            float hn[2], cn[2];
#pragma unroll
            for (int j = 0; j < 2; j++) {
                int h = h0i + j, nb = h << 2;
                float4 z = *(const float4*)&g_XZ0[((size_t)(t * BB + b) << 12) + nb];
#pragma unroll
                for (int ks = 0; ks < KSPLIT; ks++) {
                    float4 pp = __ldcg((const float4*)&g_P[ks][((size_t)b << 12) + nb]);
                    z.x += pp.x; z.y += pp.y; z.z += pp.z; z.w += pp.w;
                }
                float ig = sig_(z.x), fg = sig_(z.y), gg = tanhf(z.z), og = sig_(z.w);
                cn[j] = fg * cA[j] + ig * gg;
                hn[j] = og * tanhf(cn[j]);
                cA[j] = cn[j];
            }
            __half a0, a1, b0_, b1_, c0h, c0l, c1h, c1l;
            split_h(hn[0], a0, a1); split_h(hn[1], b0_, b1_);
            split_h(cn[0], c0h, c0l); split_h(cn[1], c1h, c1l);
            uint32_t hp = pack_h2(a0, b0_), lp = pack_h2(a1, b1_);
            size_t off = ST_OFF(h0i, b);
            *(uint32_t*)((char*)g_S0h + off) = hp; *(uint32_t*)((char*)g_S0l + off) = lp;
            *(uint32_t*)((char*)g_S1h + off) = hp; *(uint32_t*)((char*)g_S1l + off) = lp;
            off = ST_OFF(HH + h0i, b);
            *(uint32_t*)((char*)g_S0h + off) = pack_h2(c0h, c1h);
            *(uint32_t*)((char*)g_S0l + off) = pack_h2(c0l, c1l);
            if (t == TT - 1) {
                hn_base[b * HH + h0i] = hn[0]; hn_base[b * HH + h0i + 1] = hn[1];
                cn_base[b * HH + h0i] = cn[0]; cn_base[b * HH + h0i + 1] = cn[1];
            }
        }
        grid_sync(++seq * GRID_N);

        gemm_phase<1>(cta, tid, sb, mb0, uses);
        grid_sync(++seq * GRID_N);

        { // epi1
            float hn[2], cn[2];
#pragma unroll
            for (int j = 0; j < 2; j++) {
                int h = h0i + j, nb = h << 2;
                float4 z = *(const float4*)&g_b1r[nb];
#pragma unroll
                for (int ks = 0; ks < KSPLIT; ks++) {
                    float4 pp = __ldcg((const float4*)&g_P[ks][((size_t)b << 12) + nb]);
                    z.x += pp.x; z.y += pp.y; z.z += pp.z; z.w += pp.w;
                }
                float ig = sig_(z.x), fg = sig_(z.y), gg = tanhf(z.z), og = sig_(z.w);
                cn[j] = fg * cB[j] + ig * gg;
                hn[j] = og * tanhf(cn[j]);
                cB[j] = cn[j];
            }
            __half a0, a1, b0_, b1_, c0h, c0l, c1h, c1l;
            split_h(hn[0], a0, a1); split_h(hn[1], b0_, b1_);
            split_h(cn[0], c0h, c0l); split_h(cn[1], c1h, c1l);
            size_t off = ST_OFF(HH + h0i, b);
            *(uint32_t*)((char*)g_S1h + off) = pack_h2(a0, b0_);
            *(uint32_t*)((char*)g_S1l + off) = pack_h2(a1, b1_);
            off = ST_OFF(2 * HH + h0i, b);
            *(uint32_t*)((char*)g_S1h + off) = pack_h2(c0h, c1h);
            *(uint32_t*)((char*)g_S1l + off) = pack_h2(c0l, c1l);
            float* op = out + ((size_t)b * TT + t) * HH + h0i;
            op[0] = hn[0]; op[1] = hn[1];
            if (t == TT - 1) {
                hn_base[BB * HH + b * HH + h0i] = hn[0]; hn_base[BB * HH + b * HH + h0i + 1] = hn[1];
                cn_base[BB * HH + b * HH + h0i] = cn[0]; cn_base[BB * HH + b * HH + h0i + 1] = cn[1];
            }
        }
        grid_sync(++seq * GRID_N);
    }
}

extern "C" void kernel_launch(void* const* d_in, const int* in_sizes, int n_in,
                              void* d_out, int out_size) {
    (void)in_sizes; (void)n_in; (void)out_size;
    const float* x   = (const float*)d_in[0];
    const float* h0  = (const float*)d_in[1];
    const float* c0  = (const float*)d_in[2];
    const float* Wx0 = (const float*)d_in[3];
    const float* Uh0 = (const float*)d_in[4];
    const float* Vc0 = (const float*)d_in[5];
    const float* b0  = (const float*)d_in[6];
    const float* Wx1 = (const float*)d_in[7];
    const float* Uh1 = (const float*)d_in[8];
    const float* Vc1 = (const float*)d_in[9];
    const float* b1  = (const float*)d_in[10];
    float* out = (float*)d_out;

    cudaFuncSetAttribute(gemm_xz_mma, cudaFuncAttributeMaxDynamicSharedMemorySize, 2 * XZ_STAGE);
    cudaFuncSetAttribute(rnn_loop,    cudaFuncAttributeMaxDynamicSharedMemorySize, LOOP_SMEM);

    conv_x     <<<(BB * TT * IDIM) / (4 * 256), 256>>>(x);
    repack_wx0b<<<FOURH, 256>>>(Wx0, b0);
    repack_w0  <<<FOURH, 256>>>(Uh0, Vc0);
    repack_w1  <<<FOURH, 256>>>(Wx1, Uh1, Vc1, b1);
    init_state <<<(BB * HH) / 256, 256>>>(h0, c0);

    gemm_xz_mma<<<dim3(FOURH / 128, (BB * TT) / 128), 256, 2 * XZ_STAGE>>>();

    rnn_loop<<<GRID_N, 256, LOOP_SMEM>>>(out);
}

// round 14
// speedup vs baseline: 1.5285x; 1.1147x over previous
#include <cuda_runtime.h>
#include <cuda_fp16.h>
#include <math.h>
#include <stdint.h>

#define BB 64
#define TT 128
#define IDIM 4096
#define HH 1024
#define FOURH 4096
#define K0 2048
#define K1 3072
#define KSPLIT 4
#define GRID_N 128

// ---- scratch: chunk-tiled, swizzle pre-baked (16B group g of row r at g^(r&7)) ----
// fp16 scheme: x 1-plane; weights 1-plane; states hi+lo, lo consumed only for c-ranges.
__device__ __align__(128) float g_XZ0[(size_t)TT * BB * FOURH];
__device__ __align__(128) __half g_Ax[(size_t)BB * TT * IDIM];
__device__ __align__(128) __half g_Bw[(size_t)FOURH * IDIM];
__device__ __align__(128) __half g_W0[(size_t)FOURH * K0];
__device__ __align__(128) __half g_W1[(size_t)FOURH * K1];
__device__ float g_b0r[FOURH];
__device__ float g_b1r[FOURH];
__device__ __align__(128) __half g_S0h[BB * K0];
__device__ __align__(128) __half g_S0l[BB * K0];
__device__ __align__(128) __half g_S1h[BB * K1];
__device__ __align__(128) __half g_S1l[BB * K1];
__device__ float g_C0[BB * HH];
__device__ float g_C1[BB * HH];
__device__ float g_P[KSPLIT][BB * FOURH];
__device__ unsigned int g_bar;

#define AX_OFF(r,k) ( (((size_t)(((r)>>7)*64+((k)>>6)))<<14) + (size_t)(((r)&127)<<7) + (size_t)(((((k)&63)*2)^(((r)&7)<<4))) )
#define W0_OFF(n,k) ( (((size_t)(((n)>>7)*32+((k)>>6)))<<14) + (size_t)(((n)&127)<<7) + (size_t)(((((k)&63)*2)^(((n)&7)<<4))) )
#define W1_OFF(n,k) ( (((size_t)(((n)>>7)*48+((k)>>6)))<<14) + (size_t)(((n)&127)<<7) + (size_t)(((((k)&63)*2)^(((n)&7)<<4))) )
#define ST_OFF(k,b) ( (((size_t)((k)>>6))<<13) + (size_t)((b)<<7) + (size_t)(((((k)&63)*2)^(((b)&7)<<4))) )

// ---- PTX helpers ----
__device__ __forceinline__ uint32_t smem_u32(const void* p) {
    uint32_t a;
    asm("{ .reg .u64 t; cvta.to.shared.u64 t, %1; cvt.u32.u64 %0, t; }" : "=r"(a) : "l"(p));
    return a;
}
__device__ __forceinline__ void mbar_init(uint32_t m, uint32_t c) {
    asm volatile("mbarrier.init.shared.b64 [%0], %1;" :: "r"(m), "r"(c) : "memory");
}
__device__ __forceinline__ void mbar_expect(uint32_t m, uint32_t b) {
    asm volatile("mbarrier.arrive.expect_tx.shared.b64 _, [%0], %1;" :: "r"(m), "r"(b) : "memory");
}
__device__ __forceinline__ void mbar_wait(uint32_t m, uint32_t par) {
    asm volatile(
        "{\n\t.reg .pred P;\nWL%=:\n\t"
        "mbarrier.try_wait.parity.shared.b64 P, [%0], %1;\n\t"
        "@P bra.uni WD%=;\n\tbra.uni WL%=;\nWD%=:\n\t}"
        :: "r"(m), "r"(par) : "memory");
}
__device__ __forceinline__ void bulk_cp(uint32_t d, const void* s, uint32_t b, uint32_t m) {
    asm volatile("cp.async.bulk.shared::cta.global.mbarrier::complete_tx::bytes [%0], [%1], %2, [%3];"
                 :: "r"(d), "l"(s), "r"(b), "r"(m) : "memory");
}
__device__ __forceinline__ void ldsm_x4(uint32_t* r, uint32_t a) {
    asm volatile("ldmatrix.sync.aligned.m8n8.x4.shared.b16 {%0,%1,%2,%3}, [%4];"
                 : "=r"(r[0]), "=r"(r[1]), "=r"(r[2]), "=r"(r[3]) : "r"(a));
}
__device__ __forceinline__ void ldsm_x2(uint32_t* r, uint32_t a) {
    asm volatile("ldmatrix.sync.aligned.m8n8.x2.shared.b16 {%0,%1}, [%2];"
                 : "=r"(r[0]), "=r"(r[1]) : "r"(a));
}
__device__ __forceinline__ void mma_f16(float* d, const uint32_t* a, const uint32_t* b) {
    asm volatile("mma.sync.aligned.m16n8k16.row.col.f32.f16.f16.f32 "
        "{%0,%1,%2,%3}, {%4,%5,%6,%7}, {%8,%9}, {%0,%1,%2,%3};"
        : "+f"(d[0]), "+f"(d[1]), "+f"(d[2]), "+f"(d[3])
        : "r"(a[0]), "r"(a[1]), "r"(a[2]), "r"(a[3]), "r"(b[0]), "r"(b[1]));
}
__device__ __forceinline__ void split_h(float v, __half& h, __half& l) {
    h = __float2half_rn(v);
    l = __float2half_rn(v - __half2float(h));
}
__device__ __forceinline__ uint32_t pack_h2(__half a, __half b) {
    union { __half h[2]; uint32_t u; } t; t.h[0] = a; t.h[1] = b; return t.u;
}
__device__ __forceinline__ float sig_(float z) { return 1.0f / (1.0f + expf(-z)); }

__device__ __forceinline__ void grid_sync(unsigned int target) {
    asm volatile("fence.proxy.async;" ::: "memory");
    __syncthreads();
    if (threadIdx.x == 0) {
        __threadfence();
        atomicAdd(&g_bar, 1u);
        while (__ldcg(&g_bar) < target) __nanosleep(32);
        __threadfence();
    }
    __syncthreads();
}

// ---- prep kernels ----
__global__ void conv_x(const float* __restrict__ x) {
    size_t i0 = ((size_t)blockIdx.x * 256 + threadIdx.x) * 4;
    float4 v = *(const float4*)(x + i0);
    union { __half b[4]; uint2 u; } ph;
    ph.b[0] = __float2half_rn(v.x); ph.b[1] = __float2half_rn(v.y);
    ph.b[2] = __float2half_rn(v.z); ph.b[3] = __float2half_rn(v.w);
    *(uint2*)((char*)g_Ax + AX_OFF((int)(i0 >> 12), (int)(i0 & 4095))) = ph.u;
}

__global__ void repack_wx0b(const float* __restrict__ Wx0, const float* __restrict__ b0) {
    int n = blockIdx.x, g = n & 3, h = n >> 2;
    const float* src = Wx0 + (size_t)(g * HH + h) * IDIM;
    for (int i = threadIdx.x; i < IDIM; i += blockDim.x)
        *(__half*)((char*)g_Bw + AX_OFF(n, i)) = __float2half_rn(src[i]);
    if (threadIdx.x == 0) g_b0r[n] = b0[g * HH + h];
}

__global__ void repack_w0(const float* __restrict__ Uh0, const float* __restrict__ Vc0) {
    int n = blockIdx.x, g = n & 3, h = n >> 2;
    const float* u = Uh0 + (size_t)(g * HH + h) * HH;
    for (int k = threadIdx.x; k < HH; k += blockDim.x)
        *(__half*)((char*)g_W0 + W0_OFF(n, k)) = __float2half_rn(u[k]);
    int vg = (g == 0) ? 0 : (g == 1) ? 1 : (g == 3) ? 2 : -1;
    const float* v = (vg >= 0) ? (Vc0 + (size_t)(vg * HH + h) * HH) : 0;
    for (int k = threadIdx.x; k < HH; k += blockDim.x) {
        float val = (vg >= 0) ? v[k] : 0.0f;
        *(__half*)((char*)g_W0 + W0_OFF(n, HH + k)) = __float2half_rn(val);
    }
}

__global__ void repack_w1(const float* __restrict__ Wx1, const float* __restrict__ Uh1,
                          const float* __restrict__ Vc1, const float* __restrict__ b1) {
    int n = blockIdx.x, g = n & 3, h = n >> 2;
    const float* wx = Wx1 + (size_t)(g * HH + h) * HH;
    const float* uh = Uh1 + (size_t)(g * HH + h) * HH;
    for (int k = threadIdx.x; k < HH; k += blockDim.x) {
        *(__half*)((char*)g_W1 + W1_OFF(n, k))      = __float2half_rn(wx[k]);
        *(__half*)((char*)g_W1 + W1_OFF(n, HH + k)) = __float2half_rn(uh[k]);
    }
    int vg = (g == 0) ? 0 : (g == 1) ? 1 : (g == 3) ? 2 : -1;
    const float* v = (vg >= 0) ? (Vc1 + (size_t)(vg * HH + h) * HH) : 0;
    for (int k = threadIdx.x; k < HH; k += blockDim.x) {
        float val = (vg >= 0) ? v[k] : 0.0f;
        *(__half*)((char*)g_W1 + W1_OFF(n, 2 * HH + k)) = __float2half_rn(val);
    }
    if (threadIdx.x == 0) g_b1r[n] = b1[g * HH + h];
}

__global__ void init_state(const float* __restrict__ h0, const float* __restrict__ c0) {
    int idx = blockIdx.x * blockDim.x + threadIdx.x;
    if (idx == 0) g_bar = 0u;
    int b = idx >> 10, h = idx & 1023;
    __half hh, ll; float v; size_t off;
    v = h0[b * HH + h]; split_h(v, hh, ll);
    off = ST_OFF(h, b);
    *(__half*)((char*)g_S0h + off) = hh; *(__half*)((char*)g_S0l + off) = ll;
    v = c0[b * HH + h]; g_C0[idx] = v; split_h(v, hh, ll);
    off = ST_OFF(HH + h, b);
    *(__half*)((char*)g_S0h + off) = hh; *(__half*)((char*)g_S0l + off) = ll;
    v = h0[BB * HH + b * HH + h]; split_h(v, hh, ll);
    off = ST_OFF(HH + h, b);
    *(__half*)((char*)g_S1h + off) = hh; *(__half*)((char*)g_S1l + off) = ll;
    v = c0[BB * HH + b * HH + h]; g_C1[idx] = v; split_h(v, hh, ll);
    off = ST_OFF(2 * HH + h, b);
    *(__half*)((char*)g_S1h + off) = hh; *(__half*)((char*)g_S1l + off) = ll;
    off = ST_OFF(h, b);
    *(__half*)((char*)g_S1h + off) = __float2half(0.0f);
    *(__half*)((char*)g_S1l + off) = __float2half(0.0f);
}

// ---- phase A: fp16 1-plane x 1-plane W, CTA 128x128, 64 chunks of k64; stage 32KB x2 ----
#define XZ_STAGE 32768u
__global__ __launch_bounds__(256) void gemm_xz_mma() {
    extern __shared__ __align__(128) char dsm[];
    __shared__ __align__(8) unsigned long long mbars[2];
    const int tid = threadIdx.x, w = tid >> 5, l = tid & 31;
    const int wm = w & 3, wn = w >> 2;
    const int m0 = blockIdx.y * 128, n0 = blockIdx.x * 128;
    const uint32_t sb = smem_u32(dsm), mb0 = smem_u32(mbars);
    if (tid == 0) { mbar_init(mb0, 1); mbar_init(mb0 + 8, 1); }
    __syncthreads();
    const char* Ax = (const char*)g_Ax + ((size_t)blockIdx.y * 64) * 16384;
    const char* Bw = (const char*)g_Bw + ((size_t)blockIdx.x * 64) * 16384;
    auto issue = [&](int kc) {
        int st = kc & 1;
        uint32_t d = sb + st * XZ_STAGE, mb = mb0 + st * 8;
        mbar_expect(mb, XZ_STAGE);
        bulk_cp(d,         Ax + (size_t)kc * 16384, 16384, mb);
        bulk_cp(d + 16384, Bw + (size_t)kc * 16384, 16384, mb);
    };
    if (tid == 0) { issue(0); issue(1); }

    float acc[2][8][4];
#pragma unroll
    for (int a = 0; a < 2; a++)
#pragma unroll
        for (int b = 0; b < 8; b++)
#pragma unroll
            for (int c = 0; c < 4; c++) acc[a][b][c] = 0.0f;

    unsigned pst[2] = {0, 0};
    for (int kc = 0; kc < 64; kc++) {
        const int st = kc & 1;
        const uint32_t stb = sb + st * XZ_STAGE;
        mbar_wait(mb0 + st * 8, pst[st] & 1); pst[st]++;
#pragma unroll
        for (int ks = 0; ks < 4; ks++) {
            const int kb = ks * 32;
            uint32_t ah[2][4];
#pragma unroll
            for (int mt = 0; mt < 2; mt++) {
                int row = wm * 32 + mt * 16 + (l & 15);
                uint32_t ra = stb + (uint32_t)(row * 128 + ((kb + ((l >> 4) << 4)) ^ ((row & 7) << 4)));
                ldsm_x4(ah[mt], ra);
            }
#pragma unroll
            for (int nt = 0; nt < 8; nt++) {
                int row = wn * 64 + nt * 8 + (l & 7);
                uint32_t rb = stb + 16384 +
                    (uint32_t)(row * 128 + ((kb + (((l >> 3) & 1) << 4)) ^ ((row & 7) << 4)));
                uint32_t bw[2];
                ldsm_x2(bw, rb);
#pragma unroll
                for (int mt = 0; mt < 2; mt++)
                    mma_f16(acc[mt][nt], ah[mt], bw);
            }
        }
        __syncthreads();
        if (tid == 0 && kc + 2 < 64) issue(kc + 2);
    }

    const int r0 = l >> 2, cp2 = (l & 3) * 2;
#pragma unroll
    for (int mt = 0; mt < 2; mt++)
#pragma unroll
        for (int half = 0; half < 2; half++) {
            int gm = m0 + wm * 32 + mt * 16 + r0 + half * 8;
            int t = gm & (TT - 1), b = gm >> 7;
            float* dst = g_XZ0 + ((size_t)(t * BB + b) << 12);
#pragma unroll
            for (int nt = 0; nt < 8; nt++) {
                int gc = n0 + wn * 64 + nt * 8 + cp2;
                float2 v;
                v.x = acc[mt][nt][half * 2 + 0] + g_b0r[gc];
                v.y = acc[mt][nt][half * 2 + 1] + g_b0r[gc + 1];
                *(float2*)(dst + gc) = v;
            }
        }
}

// ---- persistent loop: states hi+lo, lo-mma only for c-range chunks ----
#define LP_STAGE 32768u
#define LOOP_SMEM (2u * LP_STAGE)
template <int WHICH>
__device__ __forceinline__ void issueLP(int nblk, int kseg, int kc, uint32_t sb, uint32_t mb0) {
    constexpr int NKC = (WHICH ? K1 : K0) / 64;
    constexpr int NC  = NKC / KSPLIT;
    const char* Sh = (const char*)(WHICH ? g_S1h : g_S0h);
    const char* Sl = (const char*)(WHICH ? g_S1l : g_S0l);
    const char* Wp = (const char*)(WHICH ? g_W1 : g_W0);
    const int kcA = kseg * NC + kc;
    int st = kc & 1;
    uint32_t d = sb + st * LP_STAGE, mb = mb0 + st * 8;
    mbar_expect(mb, LP_STAGE);
    bulk_cp(d,         Sh + (size_t)kcA * 8192, 8192, mb);
    bulk_cp(d + 8192,  Sl + (size_t)kcA * 8192, 8192, mb);
    bulk_cp(d + 16384, Wp + ((size_t)nblk * NKC + kcA) * 16384, 16384, mb);
}

template <int WHICH>
__device__ __forceinline__ void gemm_phase(int cta, int tid, uint32_t sb, uint32_t mb0, unsigned* uses) {
    constexpr int NC  = ((WHICH ? K1 : K0) / 64) / KSPLIT;   // 8 or 12
    constexpr int HCH = WHICH ? 32 : 16;                      // global chunks below HCH are h-range
    const int w = tid >> 5, l = tid & 31;
    const int wm = w & 3, wn = w >> 2;
    const int nblk = cta & 31, kseg = cta >> 5;

    if (tid == 0) { issueLP<WHICH>(nblk, kseg, 0, sb, mb0); issueLP<WHICH>(nblk, kseg, 1, sb, mb0); }

    float acc[8][4];
#pragma unroll
    for (int b = 0; b < 8; b++)
#pragma unroll
        for (int c = 0; c < 4; c++) acc[b][c] = 0.0f;

    for (int kc = 0; kc < NC; kc++) {
        const int st = kc & 1;
        const uint32_t stb = sb + st * LP_STAGE;
        const bool need_lo = (kseg * NC + kc) >= HCH;     // c-range: use state lo plane too
        mbar_wait(mb0 + st * 8, uses[st] & 1); uses[st]++;
#pragma unroll
        for (int ks = 0; ks < 4; ks++) {
            const int kb = ks * 32;
            uint32_t ah[4], al[4];
            int arow = wm * 16 + (l & 15);
            uint32_t ra = stb + (uint32_t)(arow * 128 + ((kb + ((l >> 4) << 4)) ^ ((arow & 7) << 4)));
            ldsm_x4(ah, ra);
            if (need_lo) ldsm_x4(al, ra + 8192);
#pragma unroll
            for (int nt = 0; nt < 8; nt++) {
                int brow = wn * 64 + nt * 8 + (l & 7);
                uint32_t rb = stb + 16384 +
                    (uint32_t)(brow * 128 + ((kb + (((l >> 3) & 1) << 4)) ^ ((brow & 7) << 4)));
                uint32_t bw[2];
                ldsm_x2(bw, rb);
                mma_f16(acc[nt], ah, bw);
                if (need_lo) mma_f16(acc[nt], al, bw);
            }
        }
        __syncthreads();
        if (tid == 0 && kc + 2 < NC) issueLP<WHICH>(nblk, kseg, kc + 2, sb, mb0);
    }

    float* dst = g_P[kseg];
    const int r0 = l >> 2, cp2 = (l & 3) * 2;
#pragma unroll
    for (int half = 0; half < 2; half++) {
        int b = wm * 16 + r0 + half * 8;
#pragma unroll
        for (int nt = 0; nt < 8; nt++) {
            int gc = nblk * 128 + wn * 64 + nt * 8 + cp2;
            *(float2*)(dst + ((size_t)b << 12) + gc) =
                make_float2(acc[nt][half * 2 + 0], acc[nt][half * 2 + 1]);
        }
    }
}

__global__ __launch_bounds__(256) void rnn_loop(float* __restrict__ out) {
    extern __shared__ __align__(128) char dsm[];
    __shared__ __align__(8) unsigned long long mbars[2];
    const int cta = blockIdx.x, tid = threadIdx.x;
    const uint32_t sb = smem_u32(dsm);
    const uint32_t mb0 = smem_u32(mbars);
    if (tid == 0) { mbar_init(mb0, 1); mbar_init(mb0 + 8, 1); }
    __syncthreads();

    const int idx0 = (cta * 256 + tid) * 2;     // two cells (same b, consecutive h)
    const int b = idx0 >> 10, h0i = idx0 & 1023;
    float cA[2] = { g_C0[idx0], g_C0[idx0 + 1] };
    float cB[2] = { g_C1[idx0], g_C1[idx0 + 1] };
    float* hn_base = out + (size_t)BB * TT * HH;
    float* cn_base = hn_base + 2 * BB * HH;
    unsigned int seq = 0;
    unsigned uses[2] = {0, 0};

    for (int t = 0; t < TT; t++) {
        gemm_phase<0>(cta, tid, sb, mb0, uses);
        grid_sync(++seq * GRID_N);

        { // epi0
            float hn[2], cn[2];
#pragma unroll
            for (int j = 0; j < 2; j++) {
                int h = h0i + j, nb = h << 2;
                float4 z = *(const float4*)&g_XZ0[((size_t)(t * BB + b) << 12) + nb];
#pragma unroll
                for (int ks = 0; ks < KSPLIT; ks++) {
                    float4 pp = __ldcg((const float4*)&g_P[ks][((size_t)b << 12) + nb]);
                    z.x += pp.x; z.y += pp.y; z.z += pp.z; z.w += pp.w;
                }
                float ig = sig_(z.x), fg = sig_(z.y), gg = tanhf(z.z), og = sig_(z.w);
                cn[j] = fg * cA[j] + ig * gg;
                hn[j] = og * tanhf(cn[j]);
                cA[j] = cn[j];
            }
            __half a0, a1, b0_, b1_, c0h, c0l, c1h, c1l;
            split_h(hn[0], a0, a1); split_h(hn[1], b0_, b1_);
            split_h(cn[0], c0h, c0l); split_h(cn[1], c1h, c1l);
            uint32_t hp = pack_h2(a0, b0_), lp = pack_h2(a1, b1_);
            size_t off = ST_OFF(h0i, b);
            *(uint32_t*)((char*)g_S0h + off) = hp; *(uint32_t*)((char*)g_S0l + off) = lp;
            *(uint32_t*)((char*)g_S1h + off) = hp; *(uint32_t*)((char*)g_S1l + off) = lp;
            off = ST_OFF(HH + h0i, b);
            *(uint32_t*)((char*)g_S0h + off) = pack_h2(c0h, c1h);
            *(uint32_t*)((char*)g_S0l + off) = pack_h2(c0l, c1l);
            if (t == TT - 1) {
                hn_base[b * HH + h0i] = hn[0]; hn_base[b * HH + h0i + 1] = hn[1];
                cn_base[b * HH + h0i] = cn[0]; cn_base[b * HH + h0i + 1] = cn[1];
            }
        }
        grid_sync(++seq * GRID_N);

        gemm_phase<1>(cta, tid, sb, mb0, uses);
        grid_sync(++seq * GRID_N);

        { // epi1
            float hn[2], cn[2];
#pragma unroll
            for (int j = 0; j < 2; j++) {
                int h = h0i + j, nb = h << 2;
                float4 z = *(const float4*)&g_b1r[nb];
#pragma unroll
                for (int ks = 0; ks < KSPLIT; ks++) {
                    float4 pp = __ldcg((const float4*)&g_P[ks][((size_t)b << 12) + nb]);
                    z.x += pp.x; z.y += pp.y; z.z += pp.z; z.w += pp.w;
                }
                float ig = sig_(z.x), fg = sig_(z.y), gg = tanhf(z.z), og = sig_(z.w);
                cn[j] = fg * cB[j] + ig * gg;
                hn[j] = og * tanhf(cn[j]);
                cB[j] = cn[j];
            }
            __half a0, a1, b0_, b1_, c0h, c0l, c1h, c1l;
            split_h(hn[0], a0, a1); split_h(hn[1], b0_, b1_);
            split_h(cn[0], c0h, c0l); split_h(cn[1], c1h, c1l);
            size_t off = ST_OFF(HH + h0i, b);
            *(uint32_t*)((char*)g_S1h + off) = pack_h2(a0, b0_);
            *(uint32_t*)((char*)g_S1l + off) = pack_h2(a1, b1_);
            off = ST_OFF(2 * HH + h0i, b);
            *(uint32_t*)((char*)g_S1h + off) = pack_h2(c0h, c1h);
            *(uint32_t*)((char*)g_S1l + off) = pack_h2(c0l, c1l);
            float* op = out + ((size_t)b * TT + t) * HH + h0i;
            op[0] = hn[0]; op[1] = hn[1];
            if (t == TT - 1) {
                hn_base[BB * HH + b * HH + h0i] = hn[0]; hn_base[BB * HH + b * HH + h0i + 1] = hn[1];
                cn_base[BB * HH + b * HH + h0i] = cn[0]; cn_base[BB * HH + b * HH + h0i + 1] = cn[1];
            }
        }
        grid_sync(++seq * GRID_N);
    }
}

extern "C" void kernel_launch(void* const* d_in, const int* in_sizes, int n_in,
                              void* d_out, int out_size) {
    (void)in_sizes; (void)n_in; (void)out_size;
    const float* x   = (const float*)d_in[0];
    const float* h0  = (const float*)d_in[1];
    const float* c0  = (const float*)d_in[2];
    const float* Wx0 = (const float*)d_in[3];
    const float* Uh0 = (const float*)d_in[4];
    const float* Vc0 = (const float*)d_in[5];
    const float* b0  = (const float*)d_in[6];
    const float* Wx1 = (const float*)d_in[7];
    const float* Uh1 = (const float*)d_in[8];
    const float* Vc1 = (const float*)d_in[9];
    const float* b1  = (const float*)d_in[10];
    float* out = (float*)d_out;

    cudaFuncSetAttribute(gemm_xz_mma, cudaFuncAttributeMaxDynamicSharedMemorySize, 2 * XZ_STAGE);
    cudaFuncSetAttribute(rnn_loop,    cudaFuncAttributeMaxDynamicSharedMemorySize, LOOP_SMEM);

    conv_x     <<<(BB * TT * IDIM) / (4 * 256), 256>>>(x);
    repack_wx0b<<<FOURH, 256>>>(Wx0, b0);
    repack_w0  <<<FOURH, 256>>>(Uh0, Vc0);
    repack_w1  <<<FOURH, 256>>>(Wx1, Uh1, Vc1, b1);
    init_state <<<(BB * HH) / 256, 256>>>(h0, c0);

    gemm_xz_mma<<<dim3(FOURH / 128, (BB * TT) / 128), 256, 2 * XZ_STAGE>>>();

    rnn_loop<<<GRID_N, 256, LOOP_SMEM>>>(out);
}